// round 11
// baseline (speedup 1.0000x reference)
#include <cuda_runtime.h>

#define LSEQ   2048
#define DMODEL 512
#define NHEAD  8
#define DH     64
#define BATCH  2
#define BH     16
#define MROWS  4096
#define SHIFT  48.0f

typedef unsigned long long ull;

__device__ __forceinline__ ull pack2(float lo, float hi) {
    ull r; asm("mov.b64 %0, {%1, %2};" : "=l"(r) : "f"(lo), "f"(hi)); return r;
}
__device__ __forceinline__ ull dup2(float x) {
    ull r; asm("mov.b64 %0, {%1, %1};" : "=l"(r) : "f"(x)); return r;
}
__device__ __forceinline__ void unpack2(ull v, float& lo, float& hi) {
    asm("mov.b64 {%0, %1}, %2;" : "=f"(lo), "=f"(hi) : "l"(v));
}
__device__ __forceinline__ ull fma2(ull a, ull b, ull c) {
    ull d; asm("fma.rn.f32x2 %0, %1, %2, %3;" : "=l"(d) : "l"(a), "l"(b), "l"(c)); return d;
}
__device__ __forceinline__ ull add2(ull a, ull b) {
    ull d; asm("add.rn.f32x2 %0, %1, %2;" : "=l"(d) : "l"(a), "l"(b)); return d;
}
__device__ __forceinline__ ull mul2(ull a, ull b) {
    ull d; asm("mul.rn.f32x2 %0, %1, %2;" : "=l"(d) : "l"(a), "l"(b)); return d;
}

// ---------------- scratch ----------------
__device__ float g_qh[BH * LSEQ * DH];
__device__ float g_kh[BH * LSEQ * DH];
__device__ float g_vh[BH * LSEQ * DH];
__device__ float g_att[MROWS * DMODEL];
__device__ float g_rowsum[BH * LSEQ];

// ---------------------------------------------------------------------------
// 64x64-tiled GEMM (f32x2): projections (unchanged, near fp32 roofline)
// ---------------------------------------------------------------------------
__global__ __launch_bounds__(256) void gemm512(const float* __restrict__ A0,
                                               const float* __restrict__ W0,
                                               const float* __restrict__ b0,
                                               float* __restrict__ o0,
                                               const float* __restrict__ A1,
                                               const float* __restrict__ W1,
                                               const float* __restrict__ b1,
                                               float* __restrict__ o1,
                                               const float* __restrict__ A2,
                                               const float* __restrict__ W2,
                                               const float* __restrict__ b2,
                                               float* __restrict__ o2,
                                               int head_layout)
{
    const float* A = A0; const float* W = W0; const float* bias = b0; float* out = o0;
    if (blockIdx.z == 1) { A = A1; W = W1; bias = b1; out = o1; }
    if (blockIdx.z == 2) { A = A2; W = W2; bias = b2; out = o2; }

    __shared__ float As[64 * 16];
    __shared__ float Ws[16 * 64];
    const int tid = threadIdx.x;
    const int tx = tid & 15, ty = tid >> 4;
    const int m0 = blockIdx.x * 64;
    const int n0 = blockIdx.y * 64;

    ull acc2[4][2] = {};

    for (int k0 = 0; k0 < DMODEL; k0 += 16) {
        {
            int idx = tid * 4;
            int r = idx >> 4, c = idx & 15;
            *(float4*)(As + idx) = *(const float4*)(A + (size_t)(m0 + r) * DMODEL + k0 + c);
            int kk = idx >> 6, cc = idx & 63;
            *(float4*)(Ws + idx) = *(const float4*)(W + (size_t)(k0 + kk) * DMODEL + n0 + cc);
        }
        __syncthreads();
#pragma unroll
        for (int kk = 0; kk < 16; kk++) {
            ulonglong2 bp = *(const ulonglong2*)(Ws + kk * 64 + tx * 4);
#pragma unroll
            for (int u = 0; u < 4; u++) {
                ull ad = dup2(As[(ty * 4 + u) * 16 + kk]);
                acc2[u][0] = fma2(ad, bp.x, acc2[u][0]);
                acc2[u][1] = fma2(ad, bp.y, acc2[u][1]);
            }
        }
        __syncthreads();
    }

    float4 bb = *(const float4*)(bias + n0 + tx * 4);
#pragma unroll
    for (int u = 0; u < 4; u++) {
        int m = m0 + ty * 4 + u;
        float4 o;
        unpack2(acc2[u][0], o.x, o.y);
        unpack2(acc2[u][1], o.z, o.w);
        o.x += bb.x; o.y += bb.y; o.z += bb.z; o.w += bb.w;
        if (head_layout) {
            int b = m >> 11, l = m & (LSEQ - 1), h = n0 >> 6;
            *(float4*)(out + (((size_t)(b * NHEAD + h) * LSEQ + l) * DH + tx * 4)) = o;
        } else {
            *(float4*)(out + (size_t)m * DMODEL + n0 + tx * 4) = o;
        }
    }
}

// ---------------------------------------------------------------------------
// Fused causal attention, f32x2, 64x64 tiles, 4x4 frags, 256 threads.
// 88KB smem -> 2 CTAs/SM (4 warps/SMSP) for latency hiding.
// Smem (floats): QT[64][68] | KT/VS[64][68] | WT[64][132]/WV[132][68] | Ps[64][68]
// ---------------------------------------------------------------------------
#define QT_OFF 0
#define KB_OFF 4352
#define WB_OFF 8704
#define PS_OFF 17680
#define SMEM_FLOATS 22032
#define SMEM_BYTES (SMEM_FLOATS * 4)

__global__ __launch_bounds__(256, 2) void attn_kernel(const float* __restrict__ qh,
                                                      const float* __restrict__ kh,
                                                      const float* __restrict__ vh,
                                                      const float* __restrict__ key_rel,
                                                      const float* __restrict__ val_rel,
                                                      float* __restrict__ aw,
                                                      float* __restrict__ att,
                                                      float* __restrict__ rowsum,
                                                      int write_aw)
{
    extern __shared__ float sm[];
    float* QT = sm + QT_OFF;   // [d][i], stride 68
    float* KT = sm + KB_OFF;   // [d][j], stride 68 (aliases VS [j][d])
    float* VS = sm + KB_OFF;
    float* WT = sm + WB_OFF;   // [d][si], stride 132 (aliases WV [s][d] stride 68)
    float* WV = sm + WB_OFF;
    float* Ps = sm + PS_OFF;   // [i][j], stride 68

    const int tid = threadIdx.x;
    const int tx = tid & 15, ty = tid >> 4;
    const int ib = 31 - blockIdx.x;       // heavy diagonal blocks first (LPT)
    const int i0 = ib * 64;
    const int bh = blockIdx.y;
    const int ntiles = ib + 1;

    // ---- QT fill (transpose): QT[d][i] ----
    const float* qbase = qh + ((size_t)bh * LSEQ + i0) * DH;
#pragma unroll
    for (int k = 0; k < 4; k++) {
        int idx = tid + k * 256;          // 1024 float4 groups
        int i = idx & 63, d4 = idx >> 6;
        float4 t = *(const float4*)(qbase + i * 64 + d4 * 4);
        QT[(4 * d4 + 0) * 68 + i] = t.x;
        QT[(4 * d4 + 1) * 68 + i] = t.y;
        QT[(4 * d4 + 2) * 68 + i] = t.z;
        QT[(4 * d4 + 3) * 68 + i] = t.w;
    }

    float rs[4];
    ull Cv[4][2], Cw[4][2];
#pragma unroll
    for (int u = 0; u < 4; u++) {
        rs[u] = 0.f;
        Cv[u][0] = 0; Cv[u][1] = 0;
        Cw[u][0] = 0; Cw[u][1] = 0;
    }

    for (int t = 0; t < ntiles; t++) {
        const int j0 = t * 64;
        const int D0 = i0 - j0 - 63;      // delta = s + D0 (WV), si-1+D0 (WT)

        __syncthreads();   // prior PV reads done / QT fill on first iter

        // ---- KT fill (transpose): KT[d][j] ----
        const float* kbase = kh + ((size_t)bh * LSEQ + j0) * DH;
#pragma unroll
        for (int k = 0; k < 4; k++) {
            int idx = tid + k * 256;
            int j = idx & 63, d4 = idx >> 6;
            float4 tt = *(const float4*)(kbase + j * 64 + d4 * 4);
            KT[(4 * d4 + 0) * 68 + j] = tt.x;
            KT[(4 * d4 + 1) * 68 + j] = tt.y;
            KT[(4 * d4 + 2) * 68 + j] = tt.z;
            KT[(4 * d4 + 3) * 68 + j] = tt.w;
        }
        // ---- WT fill: WT[d][si], si in [0,128), delta = si-1+D0 ----
#pragma unroll
        for (int k = 0; k < 8; k++) {
            int idx = tid + k * 256;      // 0..2047
            int si = idx & 127, d4 = idx >> 7;
            int delta = si - 1 + D0;
            float4 tt = make_float4(0.f, 0.f, 0.f, 0.f);
            if (delta >= 0 && delta < LSEQ)
                tt = *(const float4*)(key_rel + (size_t)(LSEQ - 1 - delta) * DH + d4 * 4);
            WT[(4 * d4 + 0) * 132 + si] = tt.x;
            WT[(4 * d4 + 1) * 132 + si] = tt.y;
            WT[(4 * d4 + 2) * 132 + si] = tt.z;
            WT[(4 * d4 + 3) * 132 + si] = tt.w;
        }
        __syncthreads();

        // ---- S: Sp[uu][v] packs rows (4ty+2uu, 4ty+2uu+1), col 4tx+v ----
        ull Sp[2][4] = {};
        {
            const float* qp = QT + 4 * ty;
            const float* kp = KT + 4 * tx;
            const float* wp = WT + (60 + 4 * ty - 4 * tx);
#pragma unroll 4
            for (int d = 0; d < 64; d++) {
                ulonglong2 aP = *(const ulonglong2*)qp;     // ap[0]=rows(0,1), ap[1]=rows(2,3)
                float4 b = *(const float4*)kp;
                ull bd[4] = { dup2(b.x), dup2(b.y), dup2(b.z), dup2(b.w) };
                float4 w0 = *(const float4*)wp;             // wv[0..3]
                float4 w1 = *(const float4*)(wp + 4);       // wv[4..7]
                float wv[8] = { w0.x, w0.y, w0.z, w0.w, w1.x, w1.y, w1.z, w1.w };
                ull P[7];
#pragma unroll
                for (int o = 1; o <= 6; o++) P[o] = pack2(wv[o], wv[o + 1]);
#pragma unroll
                for (int v = 0; v < 4; v++) {
                    Sp[0][v] = fma2(aP.x, bd[v], Sp[0][v]);
                    Sp[0][v] = fma2(aP.x, P[4 - v], Sp[0][v]);
                    Sp[1][v] = fma2(aP.y, bd[v], Sp[1][v]);
                    Sp[1][v] = fma2(aP.y, P[6 - v], Sp[1][v]);
                }
                qp += 68; kp += 68; wp += 132;
            }
        }

        // ---- exp, mask, rowsum, Ps + aw stores ----
#pragma unroll
        for (int uu = 0; uu < 2; uu++) {
            const int iA = i0 + 4 * ty + 2 * uu;
            const int iB = iA + 1;
            float e0[4], e1[4];
#pragma unroll
            for (int v = 0; v < 4; v++) {
                float sA, sB;
                unpack2(Sp[uu][v], sA, sB);
                const int j = j0 + 4 * tx + v;
                e0[v] = (j <= iA) ? __expf(sA - SHIFT) : 0.f;
                e1[v] = (j <= iB) ? __expf(sB - SHIFT) : 0.f;
                rs[2 * uu]     += e0[v];
                rs[2 * uu + 1] += e1[v];
            }
            float* pr0 = Ps + (4 * ty + 2 * uu) * 68 + 4 * tx;
            *(float4*)(pr0)      = make_float4(e0[0], e0[1], e0[2], e0[3]);
            *(float4*)(pr0 + 68) = make_float4(e1[0], e1[1], e1[2], e1[3]);
            if (write_aw) {
                *(float4*)(aw + ((size_t)bh * LSEQ + iA) * LSEQ + j0 + 4 * tx) =
                    make_float4(e0[0], e0[1], e0[2], e0[3]);
                *(float4*)(aw + ((size_t)bh * LSEQ + iB) * LSEQ + j0 + 4 * tx) =
                    make_float4(e1[0], e1[1], e1[2], e1[3]);
            }
        }
        __syncthreads();   // Ps written; KT/WT reads done

        // ---- PV fills: VS[j][d], WV[s][d] ----
        const float* vbase = vh + ((size_t)bh * LSEQ + j0) * DH;
#pragma unroll
        for (int k = 0; k < 4; k++) {
            int idx = tid + k * 256;
            int j = idx >> 4, d4 = idx & 15;
            *(float4*)(VS + j * 68 + d4 * 4) = *(const float4*)(vbase + j * 64 + d4 * 4);
        }
#pragma unroll
        for (int k = 0; k < 8; k++) {
            int idx = tid + k * 256;      // s 0..127
            int s = idx >> 4, d4 = idx & 15;
            int delta = s + D0;
            float4 tt = make_float4(0.f, 0.f, 0.f, 0.f);
            if (delta >= 0 && delta < LSEQ)
                tt = *(const float4*)(val_rel + (size_t)(LSEQ - 1 - delta) * DH + d4 * 4);
            *(float4*)(WV + s * 68 + d4 * 4) = tt;
        }
        __syncthreads();

        // ---- PV: Cv += p*V, Cw += p*Wwin (4-slot register sliding window) ----
        ulonglong2 wr[4];
#pragma unroll
        for (int u = 0; u < 4; u++)
            wr[u] = *(const ulonglong2*)(WV + (63 + 4 * ty + u) * 68 + 4 * tx);

        for (int jb = 0; jb < 64; jb += 4) {
            float4 p4[4];
#pragma unroll
            for (int u = 0; u < 4; u++)
                p4[u] = *(const float4*)(Ps + (4 * ty + u) * 68 + jb);
            ulonglong2 vv[4];
#pragma unroll
            for (int q = 0; q < 4; q++)
                vv[q] = *(const ulonglong2*)(VS + (jb + q) * 68 + 4 * tx);
#pragma unroll
            for (int q = 0; q < 4; q++) {
#pragma unroll
                for (int u = 0; u < 4; u++) {
                    ull pd = dup2(((const float*)&p4[u])[q]);
                    const int sl = (u - q) & 3;
                    Cv[u][0] = fma2(pd, vv[q].x, Cv[u][0]);
                    Cv[u][1] = fma2(pd, vv[q].y, Cv[u][1]);
                    Cw[u][0] = fma2(pd, wr[sl].x, Cw[u][0]);
                    Cw[u][1] = fma2(pd, wr[sl].y, Cw[u][1]);
                }
                const int rn = 62 + 4 * ty - jb - q;
                const int sln = (-(q + 1)) & 3;
                if (rn >= 0) {
                    wr[sln] = *(const ulonglong2*)(WV + rn * 68 + 4 * tx);
                } else {
                    wr[sln].x = 0; wr[sln].y = 0;
                }
            }
        }
    }

    // ---- finalize: reduce rowsums over 16 tx lanes, scale, store ----
#pragma unroll
    for (int u = 0; u < 4; u++) {
#pragma unroll
        for (int o = 8; o > 0; o >>= 1)
            rs[u] += __shfl_xor_sync(0xffffffffu, rs[u], o);
    }

    const int b = bh >> 3, h = bh & 7;
#pragma unroll
    for (int u = 0; u < 4; u++) {
        const int i = i0 + 4 * ty + u;
        const float inv = 1.0f / rs[u];
        if (tx == 0) rowsum[bh * LSEQ + i] = rs[u];
        ull invd = dup2(inv);
        float* dst = att + ((size_t)(b * LSEQ + i)) * DMODEL + h * DH + 4 * tx;
        ull r0 = mul2(add2(Cv[u][0], Cw[u][0]), invd);
        ull r1 = mul2(add2(Cv[u][1], Cw[u][1]), invd);
        *(ull*)(dst)     = r0;
        *(ull*)(dst + 2) = r1;
    }
}

// ---------------------------------------------------------------------------
__global__ __launch_bounds__(256) void norm_aw(float* __restrict__ aw,
                                               const float* __restrict__ rowsum)
{
    const int row = blockIdx.x;
    const int i = row & (LSEQ - 1);
    const float inv = 1.0f / rowsum[row];
    float4* p = (float4*)(aw + (size_t)row * LSEQ);
#pragma unroll
    for (int k = 0; k < 2; k++) {
        int c4 = threadIdx.x + k * 256;
        int j = c4 * 4;
        float4 v;
        if (j + 3 <= i) {
            v = p[c4];
            v.x *= inv; v.y *= inv; v.z *= inv; v.w *= inv;
        } else if (j > i) {
            v = make_float4(0.f, 0.f, 0.f, 0.f);
        } else {
            v = p[c4];
            v.x = (j     <= i) ? v.x * inv : 0.f;
            v.y = (j + 1 <= i) ? v.y * inv : 0.f;
            v.z = (j + 2 <= i) ? v.z * inv : 0.f;
            v.w = (j + 3 <= i) ? v.w * inv : 0.f;
        }
        p[c4] = v;
    }
}

// ---------------------------------------------------------------------------
extern "C" void kernel_launch(void* const* d_in, const int* in_sizes, int n_in,
                              void* d_out, int out_size)
{
    const float* q       = (const float*)d_in[0];
    const float* k       = (const float*)d_in[1];
    const float* v       = (const float*)d_in[2];
    const float* wq      = (const float*)d_in[4];
    const float* bq      = (const float*)d_in[5];
    const float* wk      = (const float*)d_in[6];
    const float* bk      = (const float*)d_in[7];
    const float* wv      = (const float*)d_in[8];
    const float* bv      = (const float*)d_in[9];
    const float* wo      = (const float*)d_in[10];
    const float* bo      = (const float*)d_in[11];
    const float* key_rel = (const float*)d_in[12];
    const float* val_rel = (const float*)d_in[13];

    float* out = (float*)d_out;
    const long long OUT_ELEMS = (long long)BATCH * LSEQ * DMODEL;
    const long long AW_ELEMS  = (long long)BH * LSEQ * LSEQ;
    const int write_aw = ((long long)out_size >= OUT_ELEMS + AW_ELEMS) ? 1 : 0;
    float* aw = out + OUT_ELEMS;

    float *qh, *kh, *vh, *att, *rsum;
    cudaGetSymbolAddress((void**)&qh,   g_qh);
    cudaGetSymbolAddress((void**)&kh,   g_kh);
    cudaGetSymbolAddress((void**)&vh,   g_vh);
    cudaGetSymbolAddress((void**)&att,  g_att);
    cudaGetSymbolAddress((void**)&rsum, g_rowsum);

    cudaFuncSetAttribute(attn_kernel, cudaFuncAttributeMaxDynamicSharedMemorySize, SMEM_BYTES);

    dim3 gGrid3(MROWS / 64, DMODEL / 64, 3);
    gemm512<<<gGrid3, 256>>>(q, wq, bq, qh,  k, wk, bk, kh,  v, wv, bv, vh, 1);

    attn_kernel<<<dim3(LSEQ / 64, BH), 256, SMEM_BYTES>>>(qh, kh, vh, key_rel, val_rel,
                                                          aw, att, rsum, write_aw);
    if (write_aw)
        norm_aw<<<BH * LSEQ, 256>>>(aw, rsum);

    dim3 gGrid(MROWS / 64, DMODEL / 64, 1);
    gemm512<<<gGrid, 256>>>(att, wo, bo, out,  att, wo, bo, out,  att, wo, bo, out, 0);
}

// round 12
// speedup vs baseline: 1.1364x; 1.1364x over previous
#include <cuda_runtime.h>

#define LSEQ   2048
#define DMODEL 512
#define NHEAD  8
#define DH     64
#define BATCH  2
#define BH     16
#define MROWS  4096
#define SHIFT  48.0f

typedef unsigned long long ull;

__device__ __forceinline__ ull pack2(float lo, float hi) {
    ull r; asm("mov.b64 %0, {%1, %2};" : "=l"(r) : "f"(lo), "f"(hi)); return r;
}
__device__ __forceinline__ ull dup2(float x) {
    ull r; asm("mov.b64 %0, {%1, %1};" : "=l"(r) : "f"(x)); return r;
}
__device__ __forceinline__ void unpack2(ull v, float& lo, float& hi) {
    asm("mov.b64 {%0, %1}, %2;" : "=f"(lo), "=f"(hi) : "l"(v));
}
__device__ __forceinline__ ull fma2(ull a, ull b, ull c) {
    ull d; asm("fma.rn.f32x2 %0, %1, %2, %3;" : "=l"(d) : "l"(a), "l"(b), "l"(c)); return d;
}
__device__ __forceinline__ ull add2(ull a, ull b) {
    ull d; asm("add.rn.f32x2 %0, %1, %2;" : "=l"(d) : "l"(a), "l"(b)); return d;
}
__device__ __forceinline__ ull mul2(ull a, ull b) {
    ull d; asm("mul.rn.f32x2 %0, %1, %2;" : "=l"(d) : "l"(a), "l"(b)); return d;
}

// ---------------- scratch ----------------
__device__ float g_qh[BH * LSEQ * DH];
__device__ float g_kh[BH * LSEQ * DH];
__device__ float g_vh[BH * LSEQ * DH];
__device__ float g_att[MROWS * DMODEL];
__device__ float g_rowsum[BH * LSEQ];

// ---------------------------------------------------------------------------
// 64x64-tiled GEMM (f32x2): projections
// ---------------------------------------------------------------------------
__global__ __launch_bounds__(256) void gemm512(const float* __restrict__ A0,
                                               const float* __restrict__ W0,
                                               const float* __restrict__ b0,
                                               float* __restrict__ o0,
                                               const float* __restrict__ A1,
                                               const float* __restrict__ W1,
                                               const float* __restrict__ b1,
                                               float* __restrict__ o1,
                                               const float* __restrict__ A2,
                                               const float* __restrict__ W2,
                                               const float* __restrict__ b2,
                                               float* __restrict__ o2,
                                               int head_layout)
{
    const float* A = A0; const float* W = W0; const float* bias = b0; float* out = o0;
    if (blockIdx.z == 1) { A = A1; W = W1; bias = b1; out = o1; }
    if (blockIdx.z == 2) { A = A2; W = W2; bias = b2; out = o2; }

    __shared__ float As[64 * 16];
    __shared__ float Ws[16 * 64];
    const int tid = threadIdx.x;
    const int tx = tid & 15, ty = tid >> 4;
    const int m0 = blockIdx.x * 64;
    const int n0 = blockIdx.y * 64;

    ull acc2[4][2] = {};

    for (int k0 = 0; k0 < DMODEL; k0 += 16) {
        {
            int idx = tid * 4;
            int r = idx >> 4, c = idx & 15;
            *(float4*)(As + idx) = *(const float4*)(A + (size_t)(m0 + r) * DMODEL + k0 + c);
            int kk = idx >> 6, cc = idx & 63;
            *(float4*)(Ws + idx) = *(const float4*)(W + (size_t)(k0 + kk) * DMODEL + n0 + cc);
        }
        __syncthreads();
#pragma unroll
        for (int kk = 0; kk < 16; kk++) {
            ulonglong2 bp = *(const ulonglong2*)(Ws + kk * 64 + tx * 4);
#pragma unroll
            for (int u = 0; u < 4; u++) {
                ull ad = dup2(As[(ty * 4 + u) * 16 + kk]);
                acc2[u][0] = fma2(ad, bp.x, acc2[u][0]);
                acc2[u][1] = fma2(ad, bp.y, acc2[u][1]);
            }
        }
        __syncthreads();
    }

    float4 bb = *(const float4*)(bias + n0 + tx * 4);
#pragma unroll
    for (int u = 0; u < 4; u++) {
        int m = m0 + ty * 4 + u;
        float4 o;
        unpack2(acc2[u][0], o.x, o.y);
        unpack2(acc2[u][1], o.z, o.w);
        o.x += bb.x; o.y += bb.y; o.z += bb.z; o.w += bb.w;
        if (head_layout) {
            int b = m >> 11, l = m & (LSEQ - 1), h = n0 >> 6;
            *(float4*)(out + (((size_t)(b * NHEAD + h) * LSEQ + l) * DH + tx * 4)) = o;
        } else {
            *(float4*)(out + (size_t)m * DMODEL + n0 + tx * 4) = o;
        }
    }
}

// ---------------------------------------------------------------------------
// Fused causal attention, f32x2, 64x64 tiles, 4x4 frags, 256 threads,
// 2 CTAs/SM. J-RANGE SPLIT: each i-tile handled by 2 CTAs (halves of its
// causal j-tiles); partial rowsums and unscaled att accumulated atomically.
// ---------------------------------------------------------------------------
#define QT_OFF 0
#define KB_OFF 4352
#define WB_OFF 8704
#define PS_OFF 17680
#define SMEM_FLOATS 22032
#define SMEM_BYTES (SMEM_FLOATS * 4)

__global__ __launch_bounds__(256, 2) void attn_kernel(const float* __restrict__ qh,
                                                      const float* __restrict__ kh,
                                                      const float* __restrict__ vh,
                                                      const float* __restrict__ key_rel,
                                                      const float* __restrict__ val_rel,
                                                      float* __restrict__ aw,
                                                      float* __restrict__ att,
                                                      float* __restrict__ rowsum,
                                                      int write_aw)
{
    extern __shared__ float sm[];
    float* QT = sm + QT_OFF;   // [d][i], stride 68
    float* KT = sm + KB_OFF;   // [d][j], stride 68 (aliases VS [j][d])
    float* VS = sm + KB_OFF;
    float* WT = sm + WB_OFF;   // [d][si], stride 132 (aliases WV [s][d] stride 68)
    float* WV = sm + WB_OFF;
    float* Ps = sm + PS_OFF;   // [i][j], stride 68

    const int tid = threadIdx.x;
    const int tx = tid & 15, ty = tid >> 4;
    const int ib = 31 - blockIdx.x;       // heavy i-tiles first (LPT)
    const int hh = blockIdx.y;            // j-range half
    const int i0 = ib * 64;
    const int bh = blockIdx.z;

    const int nt  = ib + 1;
    const int n0h = (nt + 1) >> 1;
    const int t0  = hh ? n0h : 0;
    const int t1  = hh ? nt  : n0h;
    if (t0 >= t1) return;

    // ---- QT fill (transpose): QT[d][i] ----
    const float* qbase = qh + ((size_t)bh * LSEQ + i0) * DH;
#pragma unroll
    for (int k = 0; k < 4; k++) {
        int idx = tid + k * 256;
        int i = idx & 63, d4 = idx >> 6;
        float4 t = *(const float4*)(qbase + i * 64 + d4 * 4);
        QT[(4 * d4 + 0) * 68 + i] = t.x;
        QT[(4 * d4 + 1) * 68 + i] = t.y;
        QT[(4 * d4 + 2) * 68 + i] = t.z;
        QT[(4 * d4 + 3) * 68 + i] = t.w;
    }

    float rs[4];
    ull Cv[4][2], Cw[4][2];
#pragma unroll
    for (int u = 0; u < 4; u++) {
        rs[u] = 0.f;
        Cv[u][0] = 0; Cv[u][1] = 0;
        Cw[u][0] = 0; Cw[u][1] = 0;
    }

    for (int t = t0; t < t1; t++) {
        const int j0 = t * 64;
        const int D0 = i0 - j0 - 63;

        __syncthreads();

        // ---- KT fill (transpose) ----
        const float* kbase = kh + ((size_t)bh * LSEQ + j0) * DH;
#pragma unroll
        for (int k = 0; k < 4; k++) {
            int idx = tid + k * 256;
            int j = idx & 63, d4 = idx >> 6;
            float4 tt = *(const float4*)(kbase + j * 64 + d4 * 4);
            KT[(4 * d4 + 0) * 68 + j] = tt.x;
            KT[(4 * d4 + 1) * 68 + j] = tt.y;
            KT[(4 * d4 + 2) * 68 + j] = tt.z;
            KT[(4 * d4 + 3) * 68 + j] = tt.w;
        }
        // ---- WT fill: WT[d][si], delta = si-1+D0 ----
#pragma unroll
        for (int k = 0; k < 8; k++) {
            int idx = tid + k * 256;
            int si = idx & 127, d4 = idx >> 7;
            int delta = si - 1 + D0;
            float4 tt = make_float4(0.f, 0.f, 0.f, 0.f);
            if (delta >= 0 && delta < LSEQ)
                tt = *(const float4*)(key_rel + (size_t)(LSEQ - 1 - delta) * DH + d4 * 4);
            WT[(4 * d4 + 0) * 132 + si] = tt.x;
            WT[(4 * d4 + 1) * 132 + si] = tt.y;
            WT[(4 * d4 + 2) * 132 + si] = tt.z;
            WT[(4 * d4 + 3) * 132 + si] = tt.w;
        }
        __syncthreads();

        // ---- S: Sp[uu][v] packs rows (4ty+2uu, 4ty+2uu+1) ----
        ull Sp[2][4] = {};
        {
            const float* qp = QT + 4 * ty;
            const float* kp = KT + 4 * tx;
            const float* wp = WT + (60 + 4 * ty - 4 * tx);
#pragma unroll 4
            for (int d = 0; d < 64; d++) {
                ulonglong2 aP = *(const ulonglong2*)qp;
                float4 b = *(const float4*)kp;
                ull bd[4] = { dup2(b.x), dup2(b.y), dup2(b.z), dup2(b.w) };
                float4 w0 = *(const float4*)wp;
                float4 w1 = *(const float4*)(wp + 4);
                float wv[8] = { w0.x, w0.y, w0.z, w0.w, w1.x, w1.y, w1.z, w1.w };
                ull P[7];
#pragma unroll
                for (int o = 1; o <= 6; o++) P[o] = pack2(wv[o], wv[o + 1]);
#pragma unroll
                for (int v = 0; v < 4; v++) {
                    Sp[0][v] = fma2(aP.x, bd[v], Sp[0][v]);
                    Sp[0][v] = fma2(aP.x, P[4 - v], Sp[0][v]);
                    Sp[1][v] = fma2(aP.y, bd[v], Sp[1][v]);
                    Sp[1][v] = fma2(aP.y, P[6 - v], Sp[1][v]);
                }
                qp += 68; kp += 68; wp += 132;
            }
        }

        // ---- exp, mask, rowsum, Ps + aw stores ----
#pragma unroll
        for (int uu = 0; uu < 2; uu++) {
            const int iA = i0 + 4 * ty + 2 * uu;
            const int iB = iA + 1;
            float e0[4], e1[4];
#pragma unroll
            for (int v = 0; v < 4; v++) {
                float sA, sB;
                unpack2(Sp[uu][v], sA, sB);
                const int j = j0 + 4 * tx + v;
                e0[v] = (j <= iA) ? __expf(sA - SHIFT) : 0.f;
                e1[v] = (j <= iB) ? __expf(sB - SHIFT) : 0.f;
                rs[2 * uu]     += e0[v];
                rs[2 * uu + 1] += e1[v];
            }
            float* pr0 = Ps + (4 * ty + 2 * uu) * 68 + 4 * tx;
            *(float4*)(pr0)      = make_float4(e0[0], e0[1], e0[2], e0[3]);
            *(float4*)(pr0 + 68) = make_float4(e1[0], e1[1], e1[2], e1[3]);
            if (write_aw) {
                *(float4*)(aw + ((size_t)bh * LSEQ + iA) * LSEQ + j0 + 4 * tx) =
                    make_float4(e0[0], e0[1], e0[2], e0[3]);
                *(float4*)(aw + ((size_t)bh * LSEQ + iB) * LSEQ + j0 + 4 * tx) =
                    make_float4(e1[0], e1[1], e1[2], e1[3]);
            }
        }
        __syncthreads();

        // ---- PV fills: VS[j][d], WV[s][d] ----
        const float* vbase = vh + ((size_t)bh * LSEQ + j0) * DH;
#pragma unroll
        for (int k = 0; k < 4; k++) {
            int idx = tid + k * 256;
            int j = idx >> 4, d4 = idx & 15;
            *(float4*)(VS + j * 68 + d4 * 4) = *(const float4*)(vbase + j * 64 + d4 * 4);
        }
#pragma unroll
        for (int k = 0; k < 8; k++) {
            int idx = tid + k * 256;
            int s = idx >> 4, d4 = idx & 15;
            int delta = s + D0;
            float4 tt = make_float4(0.f, 0.f, 0.f, 0.f);
            if (delta >= 0 && delta < LSEQ)
                tt = *(const float4*)(val_rel + (size_t)(LSEQ - 1 - delta) * DH + d4 * 4);
            *(float4*)(WV + s * 68 + d4 * 4) = tt;
        }
        __syncthreads();

        // ---- PV: Cv += p*V, Cw += p*Wwin (4-slot sliding window) ----
        ulonglong2 wr[4];
#pragma unroll
        for (int u = 0; u < 4; u++)
            wr[u] = *(const ulonglong2*)(WV + (63 + 4 * ty + u) * 68 + 4 * tx);

        for (int jb = 0; jb < 64; jb += 4) {
            float4 p4[4];
#pragma unroll
            for (int u = 0; u < 4; u++)
                p4[u] = *(const float4*)(Ps + (4 * ty + u) * 68 + jb);
            ulonglong2 vv[4];
#pragma unroll
            for (int q = 0; q < 4; q++)
                vv[q] = *(const ulonglong2*)(VS + (jb + q) * 68 + 4 * tx);
#pragma unroll
            for (int q = 0; q < 4; q++) {
#pragma unroll
                for (int u = 0; u < 4; u++) {
                    ull pd = dup2(((const float*)&p4[u])[q]);
                    const int sl = (u - q) & 3;
                    Cv[u][0] = fma2(pd, vv[q].x, Cv[u][0]);
                    Cv[u][1] = fma2(pd, vv[q].y, Cv[u][1]);
                    Cw[u][0] = fma2(pd, wr[sl].x, Cw[u][0]);
                    Cw[u][1] = fma2(pd, wr[sl].y, Cw[u][1]);
                }
                const int rn = 62 + 4 * ty - jb - q;
                const int sln = (-(q + 1)) & 3;
                if (rn >= 0) {
                    wr[sln] = *(const ulonglong2*)(WV + rn * 68 + 4 * tx);
                } else {
                    wr[sln].x = 0; wr[sln].y = 0;
                }
            }
        }
    }

    // ---- finalize: atomic partial rowsums + unscaled partial att ----
#pragma unroll
    for (int u = 0; u < 4; u++) {
#pragma unroll
        for (int o = 8; o > 0; o >>= 1)
            rs[u] += __shfl_xor_sync(0xffffffffu, rs[u], o);
    }

    const int b = bh >> 3, h = bh & 7;
#pragma unroll
    for (int u = 0; u < 4; u++) {
        const int i = i0 + 4 * ty + u;
        if (tx == 0) atomicAdd(&rowsum[bh * LSEQ + i], rs[u]);
        float* dst = att + ((size_t)(b * LSEQ + i)) * DMODEL + h * DH + 4 * tx;
        float a0, a1, a2, a3;
        unpack2(add2(Cv[u][0], Cw[u][0]), a0, a1);
        unpack2(add2(Cv[u][1], Cw[u][1]), a2, a3);
        atomicAdd(dst + 0, a0);
        atomicAdd(dst + 1, a1);
        atomicAdd(dst + 2, a2);
        atomicAdd(dst + 3, a3);
    }
}

// ---------------------------------------------------------------------------
// scale_att: att[m][col] *= 1/rowsum[(b*8 + col/64)*L + l]
// ---------------------------------------------------------------------------
__global__ __launch_bounds__(256) void scale_att(float* __restrict__ att,
                                                 const float* __restrict__ rowsum)
{
    int idx = blockIdx.x * 256 + threadIdx.x;   // float4 index, 524288 total
    int m = idx >> 7;                           // 128 float4 per row
    int c4 = idx & 127;
    int h = c4 >> 4;                            // 16 float4 per head
    int b = m >> 11, l = m & (LSEQ - 1);
    float inv = 1.0f / rowsum[(b * NHEAD + h) * LSEQ + l];
    float4* p = (float4*)(att + (size_t)m * DMODEL) + c4;
    float4 v = *p;
    v.x *= inv; v.y *= inv; v.z *= inv; v.w *= inv;
    *p = v;
}

// ---------------------------------------------------------------------------
__global__ __launch_bounds__(256) void norm_aw(float* __restrict__ aw,
                                               const float* __restrict__ rowsum)
{
    const int row = blockIdx.x;
    const int i = row & (LSEQ - 1);
    const float inv = 1.0f / rowsum[row];
    float4* p = (float4*)(aw + (size_t)row * LSEQ);
#pragma unroll
    for (int k = 0; k < 2; k++) {
        int c4 = threadIdx.x + k * 256;
        int j = c4 * 4;
        float4 v;
        if (j + 3 <= i) {
            v = p[c4];
            v.x *= inv; v.y *= inv; v.z *= inv; v.w *= inv;
        } else if (j > i) {
            v = make_float4(0.f, 0.f, 0.f, 0.f);
        } else {
            v = p[c4];
            v.x = (j     <= i) ? v.x * inv : 0.f;
            v.y = (j + 1 <= i) ? v.y * inv : 0.f;
            v.z = (j + 2 <= i) ? v.z * inv : 0.f;
            v.w = (j + 3 <= i) ? v.w * inv : 0.f;
        }
        p[c4] = v;
    }
}

// ---------------------------------------------------------------------------
extern "C" void kernel_launch(void* const* d_in, const int* in_sizes, int n_in,
                              void* d_out, int out_size)
{
    const float* q       = (const float*)d_in[0];
    const float* k       = (const float*)d_in[1];
    const float* v       = (const float*)d_in[2];
    const float* wq      = (const float*)d_in[4];
    const float* bq      = (const float*)d_in[5];
    const float* wk      = (const float*)d_in[6];
    const float* bk      = (const float*)d_in[7];
    const float* wv      = (const float*)d_in[8];
    const float* bv      = (const float*)d_in[9];
    const float* wo      = (const float*)d_in[10];
    const float* bo      = (const float*)d_in[11];
    const float* key_rel = (const float*)d_in[12];
    const float* val_rel = (const float*)d_in[13];

    float* out = (float*)d_out;
    const long long OUT_ELEMS = (long long)BATCH * LSEQ * DMODEL;
    const long long AW_ELEMS  = (long long)BH * LSEQ * LSEQ;
    const int write_aw = ((long long)out_size >= OUT_ELEMS + AW_ELEMS) ? 1 : 0;
    float* aw = out + OUT_ELEMS;

    float *qh, *kh, *vh, *att, *rsum;
    cudaGetSymbolAddress((void**)&qh,   g_qh);
    cudaGetSymbolAddress((void**)&kh,   g_kh);
    cudaGetSymbolAddress((void**)&vh,   g_vh);
    cudaGetSymbolAddress((void**)&att,  g_att);
    cudaGetSymbolAddress((void**)&rsum, g_rowsum);

    cudaFuncSetAttribute(attn_kernel, cudaFuncAttributeMaxDynamicSharedMemorySize, SMEM_BYTES);

    // zero accumulators (graph-capturable async memsets)
    cudaMemsetAsync(att,  0, (size_t)MROWS * DMODEL * sizeof(float));
    cudaMemsetAsync(rsum, 0, (size_t)BH * LSEQ * sizeof(float));

    dim3 gGrid3(MROWS / 64, DMODEL / 64, 3);
    gemm512<<<gGrid3, 256>>>(q, wq, bq, qh,  k, wk, bk, kh,  v, wv, bv, vh, 1);

    attn_kernel<<<dim3(32, 2, BH), 256, SMEM_BYTES>>>(qh, kh, vh, key_rel, val_rel,
                                                      aw, att, rsum, write_aw);

    scale_att<<<2048, 256>>>(att, rsum);
    if (write_aw)
        norm_aw<<<BH * LSEQ, 256>>>(aw, rsum);

    dim3 gGrid(MROWS / 64, DMODEL / 64, 1);
    gemm512<<<gGrid, 256>>>(att, wo, bo, out,  att, wo, bo, out,  att, wo, bo, out, 0);
}

// round 13
// speedup vs baseline: 1.1368x; 1.0004x over previous
#include <cuda_runtime.h>

#define LSEQ   2048
#define DMODEL 512
#define NHEAD  8
#define DH     64
#define BATCH  2
#define BH     16
#define MROWS  4096
#define SHIFT  48.0f

typedef unsigned long long ull;

__device__ __forceinline__ ull pack2(float lo, float hi) {
    ull r; asm("mov.b64 %0, {%1, %2};" : "=l"(r) : "f"(lo), "f"(hi)); return r;
}
__device__ __forceinline__ ull dup2(float x) {
    ull r; asm("mov.b64 %0, {%1, %1};" : "=l"(r) : "f"(x)); return r;
}
__device__ __forceinline__ void unpack2(ull v, float& lo, float& hi) {
    asm("mov.b64 {%0, %1}, %2;" : "=f"(lo), "=f"(hi) : "l"(v));
}
__device__ __forceinline__ ull fma2(ull a, ull b, ull c) {
    ull d; asm("fma.rn.f32x2 %0, %1, %2, %3;" : "=l"(d) : "l"(a), "l"(b), "l"(c)); return d;
}
__device__ __forceinline__ ull add2(ull a, ull b) {
    ull d; asm("add.rn.f32x2 %0, %1, %2;" : "=l"(d) : "l"(a), "l"(b)); return d;
}
__device__ __forceinline__ ull mul2(ull a, ull b) {
    ull d; asm("mul.rn.f32x2 %0, %1, %2;" : "=l"(d) : "l"(a), "l"(b)); return d;
}

// ---------------- scratch ----------------
__device__ float g_qh[BH * LSEQ * DH];
__device__ float g_kh[BH * LSEQ * DH];
__device__ float g_vh[BH * LSEQ * DH];
__device__ float g_att[MROWS * DMODEL];
__device__ float g_rowsum[BH * LSEQ];

// ---------------------------------------------------------------------------
// 64x64-tiled GEMM (f32x2): projections
// ---------------------------------------------------------------------------
__global__ __launch_bounds__(256) void gemm512(const float* __restrict__ A0,
                                               const float* __restrict__ W0,
                                               const float* __restrict__ b0,
                                               float* __restrict__ o0,
                                               const float* __restrict__ A1,
                                               const float* __restrict__ W1,
                                               const float* __restrict__ b1,
                                               float* __restrict__ o1,
                                               const float* __restrict__ A2,
                                               const float* __restrict__ W2,
                                               const float* __restrict__ b2,
                                               float* __restrict__ o2,
                                               int head_layout)
{
    const float* A = A0; const float* W = W0; const float* bias = b0; float* out = o0;
    if (blockIdx.z == 1) { A = A1; W = W1; bias = b1; out = o1; }
    if (blockIdx.z == 2) { A = A2; W = W2; bias = b2; out = o2; }

    __shared__ float As[64 * 16];
    __shared__ float Ws[16 * 64];
    const int tid = threadIdx.x;
    const int tx = tid & 15, ty = tid >> 4;
    const int m0 = blockIdx.x * 64;
    const int n0 = blockIdx.y * 64;

    ull acc2[4][2] = {};

    for (int k0 = 0; k0 < DMODEL; k0 += 16) {
        {
            int idx = tid * 4;
            int r = idx >> 4, c = idx & 15;
            *(float4*)(As + idx) = *(const float4*)(A + (size_t)(m0 + r) * DMODEL + k0 + c);
            int kk = idx >> 6, cc = idx & 63;
            *(float4*)(Ws + idx) = *(const float4*)(W + (size_t)(k0 + kk) * DMODEL + n0 + cc);
        }
        __syncthreads();
#pragma unroll
        for (int kk = 0; kk < 16; kk++) {
            ulonglong2 bp = *(const ulonglong2*)(Ws + kk * 64 + tx * 4);
#pragma unroll
            for (int u = 0; u < 4; u++) {
                ull ad = dup2(As[(ty * 4 + u) * 16 + kk]);
                acc2[u][0] = fma2(ad, bp.x, acc2[u][0]);
                acc2[u][1] = fma2(ad, bp.y, acc2[u][1]);
            }
        }
        __syncthreads();
    }

    float4 bb = *(const float4*)(bias + n0 + tx * 4);
#pragma unroll
    for (int u = 0; u < 4; u++) {
        int m = m0 + ty * 4 + u;
        float4 o;
        unpack2(acc2[u][0], o.x, o.y);
        unpack2(acc2[u][1], o.z, o.w);
        o.x += bb.x; o.y += bb.y; o.z += bb.z; o.w += bb.w;
        if (head_layout) {
            int b = m >> 11, l = m & (LSEQ - 1), h = n0 >> 6;
            *(float4*)(out + (((size_t)(b * NHEAD + h) * LSEQ + l) * DH + tx * 4)) = o;
        } else {
            *(float4*)(out + (size_t)m * DMODEL + n0 + tx * 4) = o;
        }
    }
}

// ---------------------------------------------------------------------------
// Fused causal attention, f32x2, 64x64 tiles, 4x4 frags, 256 threads,
// 2 CTAs/SM. J-RANGE SPLIT: each i-tile handled by 2 CTAs (halves of its
// causal j-tiles); partial rowsums and unscaled att accumulated atomically.
// ---------------------------------------------------------------------------
#define QT_OFF 0
#define KB_OFF 4352
#define WB_OFF 8704
#define PS_OFF 17680
#define SMEM_FLOATS 22032
#define SMEM_BYTES (SMEM_FLOATS * 4)

__global__ __launch_bounds__(256, 2) void attn_kernel(const float* __restrict__ qh,
                                                      const float* __restrict__ kh,
                                                      const float* __restrict__ vh,
                                                      const float* __restrict__ key_rel,
                                                      const float* __restrict__ val_rel,
                                                      float* __restrict__ aw,
                                                      float* __restrict__ att,
                                                      float* __restrict__ rowsum,
                                                      int write_aw)
{
    extern __shared__ float sm[];
    float* QT = sm + QT_OFF;   // [d][i], stride 68
    float* KT = sm + KB_OFF;   // [d][j], stride 68 (aliases VS [j][d])
    float* VS = sm + KB_OFF;
    float* WT = sm + WB_OFF;   // [d][si], stride 132 (aliases WV [s][d] stride 68)
    float* WV = sm + WB_OFF;
    float* Ps = sm + PS_OFF;   // [i][j], stride 68

    const int tid = threadIdx.x;
    const int tx = tid & 15, ty = tid >> 4;
    const int ib = 31 - blockIdx.x;       // heavy i-tiles first (LPT)
    const int hh = blockIdx.y;            // j-range half
    const int i0 = ib * 64;
    const int bh = blockIdx.z;

    const int nt  = ib + 1;
    const int n0h = (nt + 1) >> 1;
    const int t0  = hh ? n0h : 0;
    const int t1  = hh ? nt  : n0h;
    if (t0 >= t1) return;

    // ---- QT fill (transpose): QT[d][i] ----
    const float* qbase = qh + ((size_t)bh * LSEQ + i0) * DH;
#pragma unroll
    for (int k = 0; k < 4; k++) {
        int idx = tid + k * 256;
        int i = idx & 63, d4 = idx >> 6;
        float4 t = *(const float4*)(qbase + i * 64 + d4 * 4);
        QT[(4 * d4 + 0) * 68 + i] = t.x;
        QT[(4 * d4 + 1) * 68 + i] = t.y;
        QT[(4 * d4 + 2) * 68 + i] = t.z;
        QT[(4 * d4 + 3) * 68 + i] = t.w;
    }

    float rs[4];
    ull Cv[4][2], Cw[4][2];
#pragma unroll
    for (int u = 0; u < 4; u++) {
        rs[u] = 0.f;
        Cv[u][0] = 0; Cv[u][1] = 0;
        Cw[u][0] = 0; Cw[u][1] = 0;
    }

    for (int t = t0; t < t1; t++) {
        const int j0 = t * 64;
        const int D0 = i0 - j0 - 63;

        __syncthreads();

        // ---- KT fill (transpose) ----
        const float* kbase = kh + ((size_t)bh * LSEQ + j0) * DH;
#pragma unroll
        for (int k = 0; k < 4; k++) {
            int idx = tid + k * 256;
            int j = idx & 63, d4 = idx >> 6;
            float4 tt = *(const float4*)(kbase + j * 64 + d4 * 4);
            KT[(4 * d4 + 0) * 68 + j] = tt.x;
            KT[(4 * d4 + 1) * 68 + j] = tt.y;
            KT[(4 * d4 + 2) * 68 + j] = tt.z;
            KT[(4 * d4 + 3) * 68 + j] = tt.w;
        }
        // ---- WT fill: WT[d][si], delta = si-1+D0 ----
#pragma unroll
        for (int k = 0; k < 8; k++) {
            int idx = tid + k * 256;
            int si = idx & 127, d4 = idx >> 7;
            int delta = si - 1 + D0;
            float4 tt = make_float4(0.f, 0.f, 0.f, 0.f);
            if (delta >= 0 && delta < LSEQ)
                tt = *(const float4*)(key_rel + (size_t)(LSEQ - 1 - delta) * DH + d4 * 4);
            WT[(4 * d4 + 0) * 132 + si] = tt.x;
            WT[(4 * d4 + 1) * 132 + si] = tt.y;
            WT[(4 * d4 + 2) * 132 + si] = tt.z;
            WT[(4 * d4 + 3) * 132 + si] = tt.w;
        }
        __syncthreads();

        // ---- S: Sp[uu][v] packs rows (4ty+2uu, 4ty+2uu+1) ----
        ull Sp[2][4] = {};
        {
            const float* qp = QT + 4 * ty;
            const float* kp = KT + 4 * tx;
            const float* wp = WT + (60 + 4 * ty - 4 * tx);
#pragma unroll 4
            for (int d = 0; d < 64; d++) {
                ulonglong2 aP = *(const ulonglong2*)qp;
                float4 b = *(const float4*)kp;
                ull bd[4] = { dup2(b.x), dup2(b.y), dup2(b.z), dup2(b.w) };
                float4 w0 = *(const float4*)wp;
                float4 w1 = *(const float4*)(wp + 4);
                float wv[8] = { w0.x, w0.y, w0.z, w0.w, w1.x, w1.y, w1.z, w1.w };
                ull P[7];
#pragma unroll
                for (int o = 1; o <= 6; o++) P[o] = pack2(wv[o], wv[o + 1]);
#pragma unroll
                for (int v = 0; v < 4; v++) {
                    Sp[0][v] = fma2(aP.x, bd[v], Sp[0][v]);
                    Sp[0][v] = fma2(aP.x, P[4 - v], Sp[0][v]);
                    Sp[1][v] = fma2(aP.y, bd[v], Sp[1][v]);
                    Sp[1][v] = fma2(aP.y, P[6 - v], Sp[1][v]);
                }
                qp += 68; kp += 68; wp += 132;
            }
        }

        // ---- exp, mask, rowsum, Ps + aw stores ----
#pragma unroll
        for (int uu = 0; uu < 2; uu++) {
            const int iA = i0 + 4 * ty + 2 * uu;
            const int iB = iA + 1;
            float e0[4], e1[4];
#pragma unroll
            for (int v = 0; v < 4; v++) {
                float sA, sB;
                unpack2(Sp[uu][v], sA, sB);
                const int j = j0 + 4 * tx + v;
                e0[v] = (j <= iA) ? __expf(sA - SHIFT) : 0.f;
                e1[v] = (j <= iB) ? __expf(sB - SHIFT) : 0.f;
                rs[2 * uu]     += e0[v];
                rs[2 * uu + 1] += e1[v];
            }
            float* pr0 = Ps + (4 * ty + 2 * uu) * 68 + 4 * tx;
            *(float4*)(pr0)      = make_float4(e0[0], e0[1], e0[2], e0[3]);
            *(float4*)(pr0 + 68) = make_float4(e1[0], e1[1], e1[2], e1[3]);
            if (write_aw) {
                *(float4*)(aw + ((size_t)bh * LSEQ + iA) * LSEQ + j0 + 4 * tx) =
                    make_float4(e0[0], e0[1], e0[2], e0[3]);
                *(float4*)(aw + ((size_t)bh * LSEQ + iB) * LSEQ + j0 + 4 * tx) =
                    make_float4(e1[0], e1[1], e1[2], e1[3]);
            }
        }
        __syncthreads();

        // ---- PV fills: VS[j][d], WV[s][d] ----
        const float* vbase = vh + ((size_t)bh * LSEQ + j0) * DH;
#pragma unroll
        for (int k = 0; k < 4; k++) {
            int idx = tid + k * 256;
            int j = idx >> 4, d4 = idx & 15;
            *(float4*)(VS + j * 68 + d4 * 4) = *(const float4*)(vbase + j * 64 + d4 * 4);
        }
#pragma unroll
        for (int k = 0; k < 8; k++) {
            int idx = tid + k * 256;
            int s = idx >> 4, d4 = idx & 15;
            int delta = s + D0;
            float4 tt = make_float4(0.f, 0.f, 0.f, 0.f);
            if (delta >= 0 && delta < LSEQ)
                tt = *(const float4*)(val_rel + (size_t)(LSEQ - 1 - delta) * DH + d4 * 4);
            *(float4*)(WV + s * 68 + d4 * 4) = tt;
        }
        __syncthreads();

        // ---- PV: Cv += p*V, Cw += p*Wwin (4-slot sliding window) ----
        ulonglong2 wr[4];
#pragma unroll
        for (int u = 0; u < 4; u++)
            wr[u] = *(const ulonglong2*)(WV + (63 + 4 * ty + u) * 68 + 4 * tx);

        for (int jb = 0; jb < 64; jb += 4) {
            float4 p4[4];
#pragma unroll
            for (int u = 0; u < 4; u++)
                p4[u] = *(const float4*)(Ps + (4 * ty + u) * 68 + jb);
            ulonglong2 vv[4];
#pragma unroll
            for (int q = 0; q < 4; q++)
                vv[q] = *(const ulonglong2*)(VS + (jb + q) * 68 + 4 * tx);
#pragma unroll
            for (int q = 0; q < 4; q++) {
#pragma unroll
                for (int u = 0; u < 4; u++) {
                    ull pd = dup2(((const float*)&p4[u])[q]);
                    const int sl = (u - q) & 3;
                    Cv[u][0] = fma2(pd, vv[q].x, Cv[u][0]);
                    Cv[u][1] = fma2(pd, vv[q].y, Cv[u][1]);
                    Cw[u][0] = fma2(pd, wr[sl].x, Cw[u][0]);
                    Cw[u][1] = fma2(pd, wr[sl].y, Cw[u][1]);
                }
                const int rn = 62 + 4 * ty - jb - q;
                const int sln = (-(q + 1)) & 3;
                if (rn >= 0) {
                    wr[sln] = *(const ulonglong2*)(WV + rn * 68 + 4 * tx);
                } else {
                    wr[sln].x = 0; wr[sln].y = 0;
                }
            }
        }
    }

    // ---- finalize: atomic partial rowsums + unscaled partial att ----
#pragma unroll
    for (int u = 0; u < 4; u++) {
#pragma unroll
        for (int o = 8; o > 0; o >>= 1)
            rs[u] += __shfl_xor_sync(0xffffffffu, rs[u], o);
    }

    const int b = bh >> 3, h = bh & 7;
#pragma unroll
    for (int u = 0; u < 4; u++) {
        const int i = i0 + 4 * ty + u;
        if (tx == 0) atomicAdd(&rowsum[bh * LSEQ + i], rs[u]);
        float* dst = att + ((size_t)(b * LSEQ + i)) * DMODEL + h * DH + 4 * tx;
        float a0, a1, a2, a3;
        unpack2(add2(Cv[u][0], Cw[u][0]), a0, a1);
        unpack2(add2(Cv[u][1], Cw[u][1]), a2, a3);
        atomicAdd(dst + 0, a0);
        atomicAdd(dst + 1, a1);
        atomicAdd(dst + 2, a2);
        atomicAdd(dst + 3, a3);
    }
}

// ---------------------------------------------------------------------------
// scale_att: att[m][col] *= 1/rowsum[(b*8 + col/64)*L + l]
// ---------------------------------------------------------------------------
__global__ __launch_bounds__(256) void scale_att(float* __restrict__ att,
                                                 const float* __restrict__ rowsum)
{
    int idx = blockIdx.x * 256 + threadIdx.x;   // float4 index, 524288 total
    int m = idx >> 7;                           // 128 float4 per row
    int c4 = idx & 127;
    int h = c4 >> 4;                            // 16 float4 per head
    int b = m >> 11, l = m & (LSEQ - 1);
    float inv = 1.0f / rowsum[(b * NHEAD + h) * LSEQ + l];
    float4* p = (float4*)(att + (size_t)m * DMODEL) + c4;
    float4 v = *p;
    v.x *= inv; v.y *= inv; v.z *= inv; v.w *= inv;
    *p = v;
}

// ---------------------------------------------------------------------------
__global__ __launch_bounds__(256) void norm_aw(float* __restrict__ aw,
                                               const float* __restrict__ rowsum)
{
    const int row = blockIdx.x;
    const int i = row & (LSEQ - 1);
    const float inv = 1.0f / rowsum[row];
    float4* p = (float4*)(aw + (size_t)row * LSEQ);
#pragma unroll
    for (int k = 0; k < 2; k++) {
        int c4 = threadIdx.x + k * 256;
        int j = c4 * 4;
        float4 v;
        if (j + 3 <= i) {
            v = p[c4];
            v.x *= inv; v.y *= inv; v.z *= inv; v.w *= inv;
        } else if (j > i) {
            v = make_float4(0.f, 0.f, 0.f, 0.f);
        } else {
            v = p[c4];
            v.x = (j     <= i) ? v.x * inv : 0.f;
            v.y = (j + 1 <= i) ? v.y * inv : 0.f;
            v.z = (j + 2 <= i) ? v.z * inv : 0.f;
            v.w = (j + 3 <= i) ? v.w * inv : 0.f;
        }
        p[c4] = v;
    }
}

// ---------------------------------------------------------------------------
extern "C" void kernel_launch(void* const* d_in, const int* in_sizes, int n_in,
                              void* d_out, int out_size)
{
    const float* q       = (const float*)d_in[0];
    const float* k       = (const float*)d_in[1];
    const float* v       = (const float*)d_in[2];
    const float* wq      = (const float*)d_in[4];
    const float* bq      = (const float*)d_in[5];
    const float* wk      = (const float*)d_in[6];
    const float* bk      = (const float*)d_in[7];
    const float* wv      = (const float*)d_in[8];
    const float* bv      = (const float*)d_in[9];
    const float* wo      = (const float*)d_in[10];
    const float* bo      = (const float*)d_in[11];
    const float* key_rel = (const float*)d_in[12];
    const float* val_rel = (const float*)d_in[13];

    float* out = (float*)d_out;
    const long long OUT_ELEMS = (long long)BATCH * LSEQ * DMODEL;
    const long long AW_ELEMS  = (long long)BH * LSEQ * LSEQ;
    const int write_aw = ((long long)out_size >= OUT_ELEMS + AW_ELEMS) ? 1 : 0;
    float* aw = out + OUT_ELEMS;

    float *qh, *kh, *vh, *att, *rsum;
    cudaGetSymbolAddress((void**)&qh,   g_qh);
    cudaGetSymbolAddress((void**)&kh,   g_kh);
    cudaGetSymbolAddress((void**)&vh,   g_vh);
    cudaGetSymbolAddress((void**)&att,  g_att);
    cudaGetSymbolAddress((void**)&rsum, g_rowsum);

    cudaFuncSetAttribute(attn_kernel, cudaFuncAttributeMaxDynamicSharedMemorySize, SMEM_BYTES);

    // zero accumulators (graph-capturable async memsets)
    cudaMemsetAsync(att,  0, (size_t)MROWS * DMODEL * sizeof(float));
    cudaMemsetAsync(rsum, 0, (size_t)BH * LSEQ * sizeof(float));

    dim3 gGrid3(MROWS / 64, DMODEL / 64, 3);
    gemm512<<<gGrid3, 256>>>(q, wq, bq, qh,  k, wk, bk, kh,  v, wv, bv, vh, 1);

    attn_kernel<<<dim3(32, 2, BH), 256, SMEM_BYTES>>>(qh, kh, vh, key_rel, val_rel,
                                                      aw, att, rsum, write_aw);

    scale_att<<<2048, 256>>>(att, rsum);
    if (write_aw)
        norm_aw<<<BH * LSEQ, 256>>>(aw, rsum);

    dim3 gGrid(MROWS / 64, DMODEL / 64, 1);
    gemm512<<<gGrid, 256>>>(att, wo, bo, out,  att, wo, bo, out,  att, wo, bo, out, 0);
}

// round 15
// speedup vs baseline: 1.4923x; 1.3127x over previous
#include <cuda_runtime.h>

#define LSEQ   2048
#define DMODEL 512
#define NHEAD  8
#define DH     64
#define BATCH  2
#define BH     16
#define MROWS  4096
#define SHIFT  48.0f

typedef unsigned int u32;
typedef unsigned long long ull;

// ---------------- f32x2 helpers (projection GEMMs) ----------------
__device__ __forceinline__ ull dup2(float x) {
    ull r; asm("mov.b64 %0, {%1, %1};" : "=l"(r) : "f"(x)); return r;
}
__device__ __forceinline__ void unpack2(ull v, float& lo, float& hi) {
    asm("mov.b64 {%0, %1}, %2;" : "=f"(lo), "=f"(hi) : "l"(v));
}
__device__ __forceinline__ ull fma2(ull a, ull b, ull c) {
    ull d; asm("fma.rn.f32x2 %0, %1, %2, %3;" : "=l"(d) : "l"(a), "l"(b), "l"(c)); return d;
}

// ---------------- bf16 split + mma helpers ----------------
__device__ __forceinline__ void split2(float f0, float f1, u32& h, u32& l) {
    asm("cvt.rn.bf16x2.f32 %0, %1, %2;" : "=r"(h) : "f"(f1), "f"(f0));
    float h0 = __uint_as_float(h << 16);
    float h1 = __uint_as_float(h & 0xffff0000u);
    asm("cvt.rn.bf16x2.f32 %0, %1, %2;" : "=r"(l) : "f"(f1 - h1), "f"(f0 - h0));
}
__device__ __forceinline__ void mma_bf(float* c, const u32* a, u32 b0, u32 b1) {
    asm volatile(
        "mma.sync.aligned.m16n8k16.row.col.f32.bf16.bf16.f32 "
        "{%0,%1,%2,%3},{%4,%5,%6,%7},{%8,%9},{%0,%1,%2,%3};"
        : "+f"(c[0]), "+f"(c[1]), "+f"(c[2]), "+f"(c[3])
        : "r"(a[0]), "r"(a[1]), "r"(a[2]), "r"(a[3]), "r"(b0), "r"(b1));
}
__device__ __forceinline__ void mma3(float* c, const u32* ah, const u32* al,
                                     u32 bh0, u32 bh1, u32 bl0, u32 bl1) {
    mma_bf(c, ah, bh0, bh1);
    mma_bf(c, ah, bl0, bl1);
    mma_bf(c, al, bh0, bh1);
}

// ---------------- scratch ----------------
__device__ float g_qh[BH * LSEQ * DH];
__device__ float g_kh[BH * LSEQ * DH];
__device__ float g_vh[BH * LSEQ * DH];
__device__ float g_att[MROWS * DMODEL];
__device__ float g_rowsum[BH * LSEQ];

// ---------------------------------------------------------------------------
// 64x64-tiled GEMM (f32x2): projections
// ---------------------------------------------------------------------------
__global__ __launch_bounds__(256) void gemm512(const float* __restrict__ A0,
                                               const float* __restrict__ W0,
                                               const float* __restrict__ b0,
                                               float* __restrict__ o0,
                                               const float* __restrict__ A1,
                                               const float* __restrict__ W1,
                                               const float* __restrict__ b1,
                                               float* __restrict__ o1,
                                               const float* __restrict__ A2,
                                               const float* __restrict__ W2,
                                               const float* __restrict__ b2,
                                               float* __restrict__ o2,
                                               int head_layout)
{
    const float* A = A0; const float* W = W0; const float* bias = b0; float* out = o0;
    if (blockIdx.z == 1) { A = A1; W = W1; bias = b1; out = o1; }
    if (blockIdx.z == 2) { A = A2; W = W2; bias = b2; out = o2; }

    __shared__ float As[64 * 16];
    __shared__ float Ws[16 * 64];
    const int tid = threadIdx.x;
    const int tx = tid & 15, ty = tid >> 4;
    const int m0 = blockIdx.x * 64;
    const int n0 = blockIdx.y * 64;

    ull acc2[4][2] = {};

    for (int k0 = 0; k0 < DMODEL; k0 += 16) {
        {
            int idx = tid * 4;
            int r = idx >> 4, c = idx & 15;
            *(float4*)(As + idx) = *(const float4*)(A + (size_t)(m0 + r) * DMODEL + k0 + c);
            int kk = idx >> 6, cc = idx & 63;
            *(float4*)(Ws + idx) = *(const float4*)(W + (size_t)(k0 + kk) * DMODEL + n0 + cc);
        }
        __syncthreads();
#pragma unroll
        for (int kk = 0; kk < 16; kk++) {
            ulonglong2 bp = *(const ulonglong2*)(Ws + kk * 64 + tx * 4);
#pragma unroll
            for (int u = 0; u < 4; u++) {
                ull ad = dup2(As[(ty * 4 + u) * 16 + kk]);
                acc2[u][0] = fma2(ad, bp.x, acc2[u][0]);
                acc2[u][1] = fma2(ad, bp.y, acc2[u][1]);
            }
        }
        __syncthreads();
    }

    float4 bb = *(const float4*)(bias + n0 + tx * 4);
#pragma unroll
    for (int u = 0; u < 4; u++) {
        int m = m0 + ty * 4 + u;
        float4 o;
        unpack2(acc2[u][0], o.x, o.y);
        unpack2(acc2[u][1], o.z, o.w);
        o.x += bb.x; o.y += bb.y; o.z += bb.z; o.w += bb.w;
        if (head_layout) {
            int b = m >> 11, l = m & (LSEQ - 1), h = n0 >> 6;
            *(float4*)(out + (((size_t)(b * NHEAD + h) * LSEQ + l) * DH + tx * 4)) = o;
        } else {
            *(float4*)(out + (size_t)m * DMODEL + n0 + tx * 4) = o;
        }
    }
}

// ---------------------------------------------------------------------------
// Tensor-core attention. 64x64 tiles, 8 warps, j-split (2 CTAs/i-tile), 2/SM.
// smem u32 map: QH 0 QL 2304 | KH 4608 KL 6912 (=Vt hi/lo) |
//               WH 9216 WL 13824 (=WVt hi/lo) | RS 18432 (fp32 64x132)
// ---------------------------------------------------------------------------
#define SQH 0
#define SQL 2304
#define SKH 4608
#define SKL 6912
#define SWH 9216
#define SWL 13824
#define SRS 18432
#define SMEM_BYTES (26880 * 4)

__device__ __forceinline__ void pack4(u32* smu, int hoff, int loff, float4 f) {
    u32 h0, l0, h1, l1;
    split2(f.x, f.y, h0, l0);
    split2(f.z, f.w, h1, l1);
    smu[hoff] = h0; smu[hoff + 1] = h1;
    smu[loff] = l0; smu[loff + 1] = l1;
}

__global__ __launch_bounds__(256, 2) void attn_mma(const float* __restrict__ qh,
                                                   const float* __restrict__ kh,
                                                   const float* __restrict__ vh,
                                                   const float* __restrict__ key_rel,
                                                   const float* __restrict__ val_rel,
                                                   float* __restrict__ aw,
                                                   float* __restrict__ att,
                                                   float* __restrict__ rowsum,
                                                   int write_aw)
{
    extern __shared__ u32 smu[];
    float* smf = (float*)smu;

    const int tid = threadIdx.x;
    const int w = tid >> 5, g = w & 3, h = w >> 2;
    const int lane = tid & 31, lr = lane >> 2, lt = lane & 3;
    const int r1 = 16 * g + lr, r2 = r1 + 8;

    const int ib = 31 - blockIdx.x;
    const int hh = blockIdx.y;
    const int i0 = ib * 64;
    const int bh = blockIdx.z;
    const int nt = ib + 1, n0h = (nt + 1) >> 1;
    const int t0 = hh ? n0h : 0;
    const int t1 = hh ? nt : n0h;
    if (t0 >= t1) return;

    // Q fill: [r][d2] pairs, stride 36
    const float* qbase = qh + ((size_t)bh * LSEQ + i0) * DH;
#pragma unroll
    for (int k = 0; k < 4; k++) {
        int idx = tid + k * 256;
        int r = idx >> 4, d4 = idx & 15;
        pack4(smu, SQH + r * 36 + 2 * d4, SQL + r * 36 + 2 * d4,
              *(const float4*)(qbase + r * 64 + 4 * d4));
    }

    float rs0 = 0.f, rs1 = 0.f;
    float oacc[4][4] = {};

    for (int t = t0; t < t1; t++) {
        const int j0 = t * 64;
        const int base = i0 - j0;
        const float* kbase = kh + ((size_t)bh * LSEQ + j0) * DH;

        __syncthreads();
        // K fill [j][d2] stride 36
#pragma unroll
        for (int k = 0; k < 4; k++) {
            int idx = tid + k * 256;
            int r = idx >> 4, d4 = idx & 15;
            pack4(smu, SKH + r * 36 + 2 * d4, SKL + r * 36 + 2 * d4,
                  *(const float4*)(kbase + r * 64 + 4 * d4));
        }
        // W window fill [s][d2] stride 36, delta = base-63+s, s in [0,128)
#pragma unroll
        for (int k = 0; k < 8; k++) {
            int idx = tid + k * 256;
            int s = idx >> 4, d4 = idx & 15;
            int delta = base - 63 + s;
            float4 f = make_float4(0.f, 0.f, 0.f, 0.f);
            if (delta >= 0 && delta < LSEQ)
                f = *(const float4*)(key_rel + (size_t)(2047 - delta) * DH + 4 * d4);
            pack4(smu, SWH + s * 36 + 2 * d4, SWL + s * 36 + 2 * d4, f);
        }
        __syncthreads();

        // S1 = Q K^T (4 n-tiles) and R = Q Wwin^T (5 band tiles: mt = 2g+5h+q)
        float s1[4][4] = {};
        float ra[5][4] = {};
#pragma unroll
        for (int ks = 0; ks < 4; ks++) {
            u32 ah[4], al[4];
            int qa = r1 * 36 + 8 * ks + lt;
            ah[0] = smu[SQH + qa];     ah[1] = smu[SQH + qa + 288];
            ah[2] = smu[SQH + qa + 4]; ah[3] = smu[SQH + qa + 292];
            al[0] = smu[SQL + qa];     al[1] = smu[SQL + qa + 288];
            al[2] = smu[SQL + qa + 4]; al[3] = smu[SQL + qa + 292];
#pragma unroll
            for (int m = 0; m < 4; m++) {
                int kb = SKH + (32 * h + 8 * m + lr) * 36 + 8 * ks + lt;
                mma3(s1[m], ah, al, smu[kb], smu[kb + 4], smu[kb + 2304], smu[kb + 2308]);
            }
#pragma unroll
            for (int q = 0; q < 5; q++) {
                int wb = SWH + (8 * (2 * g + 5 * h + q) + lr) * 36 + 8 * ks + lt;
                mma3(ra[q], ah, al, smu[wb], smu[wb + 4], smu[wb + 4608], smu[wb + 4612]);
            }
        }
        // stage R band into RS fp32 [64][132]
#pragma unroll
        for (int q = 0; q < 5; q++) {
            int c0 = 8 * (2 * g + 5 * h + q) + 2 * lt;
            smf[SRS + r1 * 132 + c0]     = ra[q][0];
            smf[SRS + r1 * 132 + c0 + 1] = ra[q][1];
            smf[SRS + r2 * 132 + c0]     = ra[q][2];
            smf[SRS + r2 * 132 + c0 + 1] = ra[q][3];
        }
        __syncthreads();

        // gather rel logits: s = r - c + 63 (always in band)
        float rg[4][4];
#pragma unroll
        for (int m = 0; m < 4; m++) {
            int c = 32 * h + 8 * m + 2 * lt;
            rg[m][0] = smf[SRS + r1 * 132 + (r1 - c + 63)];
            rg[m][1] = smf[SRS + r1 * 132 + (r1 - c + 62)];
            rg[m][2] = smf[SRS + r2 * 132 + (r2 - c + 63)];
            rg[m][3] = smf[SRS + r2 * 132 + (r2 - c + 62)];
        }
        // Vt fill [d][j2] stride 36 (overwrites K region)
        const float* vbase = vh + ((size_t)bh * LSEQ + j0) * DH;
#pragma unroll
        for (int k = 0; k < 2; k++) {
            int idx = tid + k * 256;
            int j2 = idx >> 4, d4 = idx & 15;
            float4 fa = *(const float4*)(vbase + (2 * j2) * 64 + 4 * d4);
            float4 fb = *(const float4*)(vbase + (2 * j2 + 1) * 64 + 4 * d4);
            const float* pa = (const float*)&fa;
            const float* pb = (const float*)&fb;
#pragma unroll
            for (int e = 0; e < 4; e++) {
                u32 hp, lp;
                split2(pa[e], pb[e], hp, lp);
                smu[SKH + (4 * d4 + e) * 36 + j2] = hp;
                smu[SKL + (4 * d4 + e) * 36 + j2] = lp;
            }
        }
        // WVt fill [d][s2] stride 68 (overwrites W region)
#pragma unroll
        for (int k = 0; k < 4; k++) {
            int idx = tid + k * 256;
            int s2 = idx >> 4, d4 = idx & 15;
            int d0 = base - 63 + 2 * s2;
            float4 fa = make_float4(0.f, 0.f, 0.f, 0.f), fb = fa;
            if (d0 >= 0 && d0 < LSEQ)
                fa = *(const float4*)(val_rel + (size_t)(2047 - d0) * DH + 4 * d4);
            if (d0 + 1 >= 0 && d0 + 1 < LSEQ && 2 * s2 + 1 < 127)
                fb = *(const float4*)(val_rel + (size_t)(2046 - d0) * DH + 4 * d4);
            const float* pa = (const float*)&fa;
            const float* pb = (const float*)&fb;
#pragma unroll
            for (int e = 0; e < 4; e++) {
                u32 hp, lp;
                split2(pa[e], pb[e], hp, lp);
                smu[SWH + (4 * d4 + e) * 68 + s2] = hp;
                smu[SWL + (4 * d4 + e) * 68 + s2] = lp;
            }
        }
        __syncthreads();   // gathers done before P overwrites RS

        // P = exp(S1 + R - SHIFT) with causal mask; store to RS cols 0..63
#pragma unroll
        for (int m = 0; m < 4; m++) {
            int c = 32 * h + 8 * m + 2 * lt;
            int jg = j0 + c;
            float p0 = (jg     <= i0 + r1) ? __expf(s1[m][0] + rg[m][0] - SHIFT) : 0.f;
            float p1 = (jg + 1 <= i0 + r1) ? __expf(s1[m][1] + rg[m][1] - SHIFT) : 0.f;
            float p2 = (jg     <= i0 + r2) ? __expf(s1[m][2] + rg[m][2] - SHIFT) : 0.f;
            float p3 = (jg + 1 <= i0 + r2) ? __expf(s1[m][3] + rg[m][3] - SHIFT) : 0.f;
            rs0 += p0 + p1; rs1 += p2 + p3;
            smf[SRS + r1 * 132 + c]     = p0;
            smf[SRS + r1 * 132 + c + 1] = p1;
            smf[SRS + r2 * 132 + c]     = p2;
            smf[SRS + r2 * 132 + c + 1] = p3;
        }
        __syncthreads();

        // coalesced aw write from smem
        if (write_aw) {
#pragma unroll
            for (int k = 0; k < 4; k++) {
                int idx = tid + k * 256;
                int r = idx >> 4, c4 = idx & 15;
                const float* p = smf + SRS + r * 132 + 4 * c4;
                *(float4*)(aw + ((size_t)bh * LSEQ + i0 + r) * LSEQ + j0 + 4 * c4) =
                    make_float4(p[0], p[1], p[2], p[3]);
            }
        }

        // O1 = P V  (A = P split on the fly from fp32 smem)
#pragma unroll
        for (int ks = 0; ks < 4; ks++) {
            u32 ah[4], al[4];
            int b1i = SRS + r1 * 132 + 16 * ks + 2 * lt;
            int b2i = SRS + r2 * 132 + 16 * ks + 2 * lt;
            split2(smf[b1i],     smf[b1i + 1], ah[0], al[0]);
            split2(smf[b2i],     smf[b2i + 1], ah[1], al[1]);
            split2(smf[b1i + 8], smf[b1i + 9], ah[2], al[2]);
            split2(smf[b2i + 8], smf[b2i + 9], ah[3], al[3]);
#pragma unroll
            for (int m = 0; m < 4; m++) {
                int vb = SKH + (32 * h + 8 * m + lr) * 36 + 8 * ks + lt;
                mma3(oacc[m], ah, al, smu[vb], smu[vb + 4], smu[vb + 2304], smu[vb + 2308]);
            }
        }
        // O2 = Pd WVwin, ks restricted to band [g, g+4]; Pd[r][k] = P[r][r-k+63]
#pragma unroll
        for (int q = 0; q < 5; q++) {
            int ks = g + q;
            int k0 = 16 * ks + 2 * lt;
            u32 ah[4], al[4];
            int c1a = r1 - k0 + 63, c2a = r2 - k0 + 63;
#pragma unroll
            for (int half = 0; half < 2; half++) {
                int c1 = c1a - 8 * half, c2 = c2a - 8 * half;
                float x0 = (c1 >= 0 && c1 <= 63) ? smf[SRS + r1 * 132 + c1] : 0.f;
                float x1 = (c1 >= 1 && c1 <= 64) ? smf[SRS + r1 * 132 + c1 - 1] : 0.f;
                split2(x0, x1, ah[2 * half], al[2 * half]);
                float y0 = (c2 >= 0 && c2 <= 63) ? smf[SRS + r2 * 132 + c2] : 0.f;
                float y1 = (c2 >= 1 && c2 <= 64) ? smf[SRS + r2 * 132 + c2 - 1] : 0.f;
                split2(y0, y1, ah[2 * half + 1], al[2 * half + 1]);
            }
#pragma unroll
            for (int m = 0; m < 4; m++) {
                int wb = SWH + (32 * h + 8 * m + lr) * 68 + 8 * ks + lt;
                mma3(oacc[m], ah, al, smu[wb], smu[wb + 4], smu[wb + 4608], smu[wb + 4612]);
            }
        }
    }

    // finalize: reduce rowsums over lt group; BOTH column-half warps contribute
    rs0 += __shfl_xor_sync(0xffffffffu, rs0, 1);
    rs0 += __shfl_xor_sync(0xffffffffu, rs0, 2);
    rs1 += __shfl_xor_sync(0xffffffffu, rs1, 1);
    rs1 += __shfl_xor_sync(0xffffffffu, rs1, 2);
    if (lt == 0) {
        atomicAdd(&rowsum[bh * LSEQ + i0 + r1], rs0);
        atomicAdd(&rowsum[bh * LSEQ + i0 + r2], rs1);
    }

    const int b = bh >> 3, head = bh & 7;
#pragma unroll
    for (int m = 0; m < 4; m++) {
        int d = head * DH + 32 * h + 8 * m + 2 * lt;
        float* d1 = att + ((size_t)(b * LSEQ + i0 + r1)) * DMODEL + d;
        float* d2 = att + ((size_t)(b * LSEQ + i0 + r2)) * DMODEL + d;
        atomicAdd(d1,     oacc[m][0]);
        atomicAdd(d1 + 1, oacc[m][1]);
        atomicAdd(d2,     oacc[m][2]);
        atomicAdd(d2 + 1, oacc[m][3]);
    }
}

// ---------------------------------------------------------------------------
__global__ __launch_bounds__(256) void scale_att(float* __restrict__ att,
                                                 const float* __restrict__ rowsum)
{
    int idx = blockIdx.x * 256 + threadIdx.x;
    int m = idx >> 7, c4 = idx & 127;
    int h = c4 >> 4;
    int b = m >> 11, l = m & (LSEQ - 1);
    float inv = 1.0f / rowsum[(b * NHEAD + h) * LSEQ + l];
    float4* p = (float4*)(att + (size_t)m * DMODEL) + c4;
    float4 v = *p;
    v.x *= inv; v.y *= inv; v.z *= inv; v.w *= inv;
    *p = v;
}

__global__ __launch_bounds__(256) void norm_aw(float* __restrict__ aw,
                                               const float* __restrict__ rowsum)
{
    const int row = blockIdx.x;
    const int i = row & (LSEQ - 1);
    const float inv = 1.0f / rowsum[row];
    float4* p = (float4*)(aw + (size_t)row * LSEQ);
#pragma unroll
    for (int k = 0; k < 2; k++) {
        int c4 = threadIdx.x + k * 256;
        int j = c4 * 4;
        float4 v;
        if (j + 3 <= i) {
            v = p[c4];
            v.x *= inv; v.y *= inv; v.z *= inv; v.w *= inv;
        } else if (j > i) {
            v = make_float4(0.f, 0.f, 0.f, 0.f);
        } else {
            v = p[c4];
            v.x = (j     <= i) ? v.x * inv : 0.f;
            v.y = (j + 1 <= i) ? v.y * inv : 0.f;
            v.z = (j + 2 <= i) ? v.z * inv : 0.f;
            v.w = (j + 3 <= i) ? v.w * inv : 0.f;
        }
        p[c4] = v;
    }
}

// ---------------------------------------------------------------------------
extern "C" void kernel_launch(void* const* d_in, const int* in_sizes, int n_in,
                              void* d_out, int out_size)
{
    const float* q       = (const float*)d_in[0];
    const float* k       = (const float*)d_in[1];
    const float* v       = (const float*)d_in[2];
    const float* wq      = (const float*)d_in[4];
    const float* bq      = (const float*)d_in[5];
    const float* wk      = (const float*)d_in[6];
    const float* bk      = (const float*)d_in[7];
    const float* wv      = (const float*)d_in[8];
    const float* bv      = (const float*)d_in[9];
    const float* wo      = (const float*)d_in[10];
    const float* bo      = (const float*)d_in[11];
    const float* key_rel = (const float*)d_in[12];
    const float* val_rel = (const float*)d_in[13];

    float* out = (float*)d_out;
    const long long OUT_ELEMS = (long long)BATCH * LSEQ * DMODEL;
    const long long AW_ELEMS  = (long long)BH * LSEQ * LSEQ;
    const int write_aw = ((long long)out_size >= OUT_ELEMS + AW_ELEMS) ? 1 : 0;
    float* aw = out + OUT_ELEMS;

    float *qh, *kh, *vh, *att, *rsum;
    cudaGetSymbolAddress((void**)&qh,   g_qh);
    cudaGetSymbolAddress((void**)&kh,   g_kh);
    cudaGetSymbolAddress((void**)&vh,   g_vh);
    cudaGetSymbolAddress((void**)&att,  g_att);
    cudaGetSymbolAddress((void**)&rsum, g_rowsum);

    cudaFuncSetAttribute(attn_mma, cudaFuncAttributeMaxDynamicSharedMemorySize, SMEM_BYTES);

    cudaMemsetAsync(att,  0, (size_t)MROWS * DMODEL * sizeof(float));
    cudaMemsetAsync(rsum, 0, (size_t)BH * LSEQ * sizeof(float));

    dim3 gGrid3(MROWS / 64, DMODEL / 64, 3);
    gemm512<<<gGrid3, 256>>>(q, wq, bq, qh,  k, wk, bk, kh,  v, wv, bv, vh, 1);

    attn_mma<<<dim3(32, 2, BH), 256, SMEM_BYTES>>>(qh, kh, vh, key_rel, val_rel,
                                                   aw, att, rsum, write_aw);

    scale_att<<<2048, 256>>>(att, rsum);
    if (write_aw)
        norm_aw<<<BH * LSEQ, 256>>>(aw, rsum);

    dim3 gGrid(MROWS / 64, DMODEL / 64, 1);
    gemm512<<<gGrid, 256>>>(att, wo, bo, out,  att, wo, bo, out,  att, wo, bo, out, 0);
}

// round 16
// speedup vs baseline: 1.5115x; 1.0128x over previous
#include <cuda_runtime.h>

#define LSEQ   2048
#define DMODEL 512
#define NHEAD  8
#define DH     64
#define BATCH  2
#define BH     16
#define MROWS  4096
#define SHIFT  48.0f

typedef unsigned int u32;
typedef unsigned long long ull;

// ---------------- f32x2 helpers (projection GEMMs) ----------------
__device__ __forceinline__ ull dup2(float x) {
    ull r; asm("mov.b64 %0, {%1, %1};" : "=l"(r) : "f"(x)); return r;
}
__device__ __forceinline__ void unpack2(ull v, float& lo, float& hi) {
    asm("mov.b64 {%0, %1}, %2;" : "=f"(lo), "=f"(hi) : "l"(v));
}
__device__ __forceinline__ ull fma2(ull a, ull b, ull c) {
    ull d; asm("fma.rn.f32x2 %0, %1, %2, %3;" : "=l"(d) : "l"(a), "l"(b), "l"(c)); return d;
}

// ---------------- bf16 split + mma helpers ----------------
__device__ __forceinline__ void split2(float f0, float f1, u32& h, u32& l) {
    asm("cvt.rn.bf16x2.f32 %0, %1, %2;" : "=r"(h) : "f"(f1), "f"(f0));
    float h0 = __uint_as_float(h << 16);
    float h1 = __uint_as_float(h & 0xffff0000u);
    asm("cvt.rn.bf16x2.f32 %0, %1, %2;" : "=r"(l) : "f"(f1 - h1), "f"(f0 - h0));
}
__device__ __forceinline__ void mma_bf(float* c, const u32* a, u32 b0, u32 b1) {
    asm volatile(
        "mma.sync.aligned.m16n8k16.row.col.f32.bf16.bf16.f32 "
        "{%0,%1,%2,%3},{%4,%5,%6,%7},{%8,%9},{%0,%1,%2,%3};"
        : "+f"(c[0]), "+f"(c[1]), "+f"(c[2]), "+f"(c[3])
        : "r"(a[0]), "r"(a[1]), "r"(a[2]), "r"(a[3]), "r"(b0), "r"(b1));
}
__device__ __forceinline__ void mma3(float* c, const u32* ah, const u32* al,
                                     u32 bh0, u32 bh1, u32 bl0, u32 bl1) {
    mma_bf(c, ah, bh0, bh1);
    mma_bf(c, ah, bl0, bl1);
    mma_bf(c, al, bh0, bh1);
}

// ---------------- scratch ----------------
__device__ float g_vh[BH * LSEQ * DH];
__device__ float g_att[MROWS * DMODEL];
__device__ float g_rowsum[BH * LSEQ];
// pre-packed bf16 hi/lo: Q (z=0), K (z=1), d-pairs: [z][bh*L + l][32]
__device__ u32 g_qkp_h[2 * BH * LSEQ * 32];
__device__ u32 g_qkp_l[2 * BH * LSEQ * 32];
// key_rel reversed, d-pair packed: [delta][32]
__device__ u32 g_kr_h[LSEQ * 32];
__device__ u32 g_kr_l[LSEQ * 32];
// val_rel reversed, delta-pair packed: entry idx <-> deltas (2(idx-1)+1, 2(idx-1)+2)
__device__ u32 g_vp_h[1025 * 64];
__device__ u32 g_vp_l[1025 * 64];

// ---------------------------------------------------------------------------
// prep: pre-split key_rel / val_rel into packed bf16 hi/lo
// ---------------------------------------------------------------------------
__global__ __launch_bounds__(256) void prep_rel(const float* __restrict__ key_rel,
                                                const float* __restrict__ val_rel)
{
    int tid = blockIdx.x * 256 + threadIdx.x;   // 32768 threads
    {   // KR: [delta][d-pairs]
        int delta = tid >> 4, d4 = tid & 15;
        float4 f = *(const float4*)(key_rel + (size_t)(2047 - delta) * DH + 4 * d4);
        u32 h0, l0, h1, l1;
        split2(f.x, f.y, h0, l0);
        split2(f.z, f.w, h1, l1);
        g_kr_h[delta * 32 + 2 * d4] = h0; g_kr_h[delta * 32 + 2 * d4 + 1] = h1;
        g_kr_l[delta * 32 + 2 * d4] = l0; g_kr_l[delta * 32 + 2 * d4 + 1] = l1;
    }
    if (tid < 1025 * 16) {   // VP: [idx][d], delta-pair packed
        int idx = tid >> 4, d4 = tid & 15;
        int m = idx - 1;
        int da = 2 * m + 1, db = 2 * m + 2;
        float4 fa = make_float4(0.f, 0.f, 0.f, 0.f), fb = fa;
        if (da >= 0 && da < LSEQ)
            fa = *(const float4*)(val_rel + (size_t)(2047 - da) * DH + 4 * d4);
        if (db >= 0 && db < LSEQ)
            fb = *(const float4*)(val_rel + (size_t)(2047 - db) * DH + 4 * d4);
        const float* pa = (const float*)&fa;
        const float* pb = (const float*)&fb;
#pragma unroll
        for (int e = 0; e < 4; e++) {
            u32 hp, lp;
            split2(pa[e], pb[e], hp, lp);
            g_vp_h[idx * 64 + 4 * d4 + e] = hp;
            g_vp_l[idx * 64 + 4 * d4 + e] = lp;
        }
    }
}

// ---------------------------------------------------------------------------
// 64x64-tiled GEMM (f32x2). head_layout=1: z=0/1 write packed bf16 Q/K,
// z=2 writes fp32 V in head layout. head_layout=0: plain fp32 GEMM.
// ---------------------------------------------------------------------------
__global__ __launch_bounds__(256) void gemm512(const float* __restrict__ A0,
                                               const float* __restrict__ W0,
                                               const float* __restrict__ b0,
                                               float* __restrict__ o0,
                                               const float* __restrict__ A1,
                                               const float* __restrict__ W1,
                                               const float* __restrict__ b1,
                                               const float* __restrict__ A2,
                                               const float* __restrict__ W2,
                                               const float* __restrict__ b2,
                                               float* __restrict__ o2,
                                               int head_layout)
{
    const float* A = A0; const float* W = W0; const float* bias = b0;
    if (blockIdx.z == 1) { A = A1; W = W1; bias = b1; }
    if (blockIdx.z == 2) { A = A2; W = W2; bias = b2; }

    __shared__ float As[64 * 16];
    __shared__ float Ws[16 * 64];
    const int tid = threadIdx.x;
    const int tx = tid & 15, ty = tid >> 4;
    const int m0 = blockIdx.x * 64;
    const int n0 = blockIdx.y * 64;

    ull acc2[4][2] = {};

    for (int k0 = 0; k0 < DMODEL; k0 += 16) {
        {
            int idx = tid * 4;
            int r = idx >> 4, c = idx & 15;
            *(float4*)(As + idx) = *(const float4*)(A + (size_t)(m0 + r) * DMODEL + k0 + c);
            int kk = idx >> 6, cc = idx & 63;
            *(float4*)(Ws + idx) = *(const float4*)(W + (size_t)(k0 + kk) * DMODEL + n0 + cc);
        }
        __syncthreads();
#pragma unroll
        for (int kk = 0; kk < 16; kk++) {
            ulonglong2 bp = *(const ulonglong2*)(Ws + kk * 64 + tx * 4);
#pragma unroll
            for (int u = 0; u < 4; u++) {
                ull ad = dup2(As[(ty * 4 + u) * 16 + kk]);
                acc2[u][0] = fma2(ad, bp.x, acc2[u][0]);
                acc2[u][1] = fma2(ad, bp.y, acc2[u][1]);
            }
        }
        __syncthreads();
    }

    float4 bb = *(const float4*)(bias + n0 + tx * 4);
#pragma unroll
    for (int u = 0; u < 4; u++) {
        int m = m0 + ty * 4 + u;
        float4 o;
        unpack2(acc2[u][0], o.x, o.y);
        unpack2(acc2[u][1], o.z, o.w);
        o.x += bb.x; o.y += bb.y; o.z += bb.z; o.w += bb.w;
        if (head_layout) {
            int b = m >> 11, l = m & (LSEQ - 1), h = n0 >> 6;
            if (blockIdx.z == 2) {
                *(float4*)(o2 + (((size_t)(b * NHEAD + h) * LSEQ + l) * DH + tx * 4)) = o;
            } else {
                u32 h0, l0, h1, l1;
                split2(o.x, o.y, h0, l0);
                split2(o.z, o.w, h1, l1);
                size_t base = (size_t)blockIdx.z * (BH * LSEQ * 32)
                            + ((size_t)(b * NHEAD + h) * LSEQ + l) * 32 + 2 * tx;
                g_qkp_h[base] = h0; g_qkp_h[base + 1] = h1;
                g_qkp_l[base] = l0; g_qkp_l[base + 1] = l1;
            }
        } else {
            *(float4*)(o0 + (size_t)m * DMODEL + n0 + tx * 4) = o;
        }
    }
}

// ---------------------------------------------------------------------------
// Tensor-core attention. 64x64 tiles, 8 warps, j-split (2 CTAs/i-tile), 2/SM.
// smem u32 map: QH 0 QL 2304 | KH 4608 KL 6912 (=Vt hi/lo) |
//               WH 9216 WL 13824 (=WVt hi/lo) | RS 18432 (fp32 64x132)
// All fill-side bf16 splitting is pre-computed (g_qkp / g_kr / g_vp),
// except Vt (j-pair packing of V, done in-kernel).
// ---------------------------------------------------------------------------
#define SQH 0
#define SQL 2304
#define SKH 4608
#define SKL 6912
#define SWH 9216
#define SWL 13824
#define SRS 18432
#define SMEM_BYTES (26880 * 4)

__global__ __launch_bounds__(256, 2) void attn_mma(const float* __restrict__ vh,
                                                   float* __restrict__ aw,
                                                   float* __restrict__ att,
                                                   float* __restrict__ rowsum,
                                                   int write_aw)
{
    extern __shared__ u32 smu[];
    float* smf = (float*)smu;

    const int tid = threadIdx.x;
    const int w = tid >> 5, g = w & 3, h = w >> 2;
    const int lane = tid & 31, lr = lane >> 2, lt = lane & 3;
    const int r1 = 16 * g + lr, r2 = r1 + 8;

    const int ib = 31 - blockIdx.x;
    const int hh = blockIdx.y;
    const int i0 = ib * 64;
    const int bh = blockIdx.z;
    const int nt = ib + 1, n0h = (nt + 1) >> 1;
    const int t0 = hh ? n0h : 0;
    const int t1 = hh ? nt : n0h;
    if (t0 >= t1) return;

    // Q fill: plain ull copies of pre-packed pairs
    const u32* qph = g_qkp_h + ((size_t)bh * LSEQ + i0) * 32;
    const u32* qpl = g_qkp_l + ((size_t)bh * LSEQ + i0) * 32;
#pragma unroll
    for (int k = 0; k < 4; k++) {
        int idx = tid + k * 256;
        int r = idx >> 4, d4 = idx & 15;
        ull hv = *(const ull*)(qph + r * 32 + 2 * d4);
        ull lv = *(const ull*)(qpl + r * 32 + 2 * d4);
        smu[SQH + r * 36 + 2 * d4]     = (u32)hv;
        smu[SQH + r * 36 + 2 * d4 + 1] = (u32)(hv >> 32);
        smu[SQL + r * 36 + 2 * d4]     = (u32)lv;
        smu[SQL + r * 36 + 2 * d4 + 1] = (u32)(lv >> 32);
    }

    float rs0 = 0.f, rs1 = 0.f;
    float oacc[4][4] = {};

    for (int t = t0; t < t1; t++) {
        const int j0 = t * 64;
        const int base = i0 - j0;

        __syncthreads();
        // K fill: pre-packed copies
        const u32* kph = g_qkp_h + (size_t)(BH * LSEQ * 32) + ((size_t)bh * LSEQ + j0) * 32;
        const u32* kpl = g_qkp_l + (size_t)(BH * LSEQ * 32) + ((size_t)bh * LSEQ + j0) * 32;
#pragma unroll
        for (int k = 0; k < 4; k++) {
            int idx = tid + k * 256;
            int r = idx >> 4, d4 = idx & 15;
            ull hv = *(const ull*)(kph + r * 32 + 2 * d4);
            ull lv = *(const ull*)(kpl + r * 32 + 2 * d4);
            smu[SKH + r * 36 + 2 * d4]     = (u32)hv;
            smu[SKH + r * 36 + 2 * d4 + 1] = (u32)(hv >> 32);
            smu[SKL + r * 36 + 2 * d4]     = (u32)lv;
            smu[SKL + r * 36 + 2 * d4 + 1] = (u32)(lv >> 32);
        }
        // W window fill from g_kr (delta = base-63+s, s in [0,128))
#pragma unroll
        for (int k = 0; k < 8; k++) {
            int idx = tid + k * 256;
            int s = idx >> 4, d4 = idx & 15;
            int delta = base - 63 + s;
            u32 a = 0, b = 0, c = 0, d = 0;
            if (delta >= 0 && delta < LSEQ) {
                ull hv = *(const ull*)(g_kr_h + delta * 32 + 2 * d4);
                ull lv = *(const ull*)(g_kr_l + delta * 32 + 2 * d4);
                a = (u32)hv; b = (u32)(hv >> 32);
                c = (u32)lv; d = (u32)(lv >> 32);
            }
            smu[SWH + s * 36 + 2 * d4]     = a;
            smu[SWH + s * 36 + 2 * d4 + 1] = b;
            smu[SWL + s * 36 + 2 * d4]     = c;
            smu[SWL + s * 36 + 2 * d4 + 1] = d;
        }
        __syncthreads();

        // S1 = Q K^T (4 n-tiles) and R = Q Wwin^T (5 band tiles)
        float s1[4][4] = {};
        float ra[5][4] = {};
#pragma unroll
        for (int ks = 0; ks < 4; ks++) {
            u32 ah[4], al[4];
            int qa = r1 * 36 + 8 * ks + lt;
            ah[0] = smu[SQH + qa];     ah[1] = smu[SQH + qa + 288];
            ah[2] = smu[SQH + qa + 4]; ah[3] = smu[SQH + qa + 292];
            al[0] = smu[SQL + qa];     al[1] = smu[SQL + qa + 288];
            al[2] = smu[SQL + qa + 4]; al[3] = smu[SQL + qa + 292];
#pragma unroll
            for (int m = 0; m < 4; m++) {
                int kb = SKH + (32 * h + 8 * m + lr) * 36 + 8 * ks + lt;
                mma3(s1[m], ah, al, smu[kb], smu[kb + 4], smu[kb + 2304], smu[kb + 2308]);
            }
#pragma unroll
            for (int q = 0; q < 5; q++) {
                int wb = SWH + (8 * (2 * g + 5 * h + q) + lr) * 36 + 8 * ks + lt;
                mma3(ra[q], ah, al, smu[wb], smu[wb + 4], smu[wb + 4608], smu[wb + 4612]);
            }
        }
        // stage R band into RS fp32 [64][132]
#pragma unroll
        for (int q = 0; q < 5; q++) {
            int c0 = 8 * (2 * g + 5 * h + q) + 2 * lt;
            smf[SRS + r1 * 132 + c0]     = ra[q][0];
            smf[SRS + r1 * 132 + c0 + 1] = ra[q][1];
            smf[SRS + r2 * 132 + c0]     = ra[q][2];
            smf[SRS + r2 * 132 + c0 + 1] = ra[q][3];
        }
        __syncthreads();

        // gather rel logits: s = r - c + 63
        float rg[4][4];
#pragma unroll
        for (int m = 0; m < 4; m++) {
            int c = 32 * h + 8 * m + 2 * lt;
            rg[m][0] = smf[SRS + r1 * 132 + (r1 - c + 63)];
            rg[m][1] = smf[SRS + r1 * 132 + (r1 - c + 62)];
            rg[m][2] = smf[SRS + r2 * 132 + (r2 - c + 63)];
            rg[m][3] = smf[SRS + r2 * 132 + (r2 - c + 62)];
        }
        // Vt fill [d][j2] stride 36 (overwrites K region) — in-kernel split
        const float* vbase = vh + ((size_t)bh * LSEQ + j0) * DH;
#pragma unroll
        for (int k = 0; k < 2; k++) {
            int idx = tid + k * 256;
            int j2 = idx >> 4, d4 = idx & 15;
            float4 fa = *(const float4*)(vbase + (2 * j2) * 64 + 4 * d4);
            float4 fb = *(const float4*)(vbase + (2 * j2 + 1) * 64 + 4 * d4);
            const float* pa = (const float*)&fa;
            const float* pb = (const float*)&fb;
#pragma unroll
            for (int e = 0; e < 4; e++) {
                u32 hp, lp;
                split2(pa[e], pb[e], hp, lp);
                smu[SKH + (4 * d4 + e) * 36 + j2] = hp;
                smu[SKL + (4 * d4 + e) * 36 + j2] = lp;
            }
        }
        // WVt fill [d][s2] stride 68 from g_vp (overwrites W region)
#pragma unroll
        for (int k = 0; k < 4; k++) {
            int idx = tid + k * 256;
            int s2 = idx >> 4, d4 = idx & 15;
            int vidx = (base >> 1) + s2 - 31;
            uint4 hv = make_uint4(0u, 0u, 0u, 0u), lv = hv;
            if (vidx >= 0 && vidx <= 1024) {
                hv = *(const uint4*)(g_vp_h + vidx * 64 + 4 * d4);
                lv = *(const uint4*)(g_vp_l + vidx * 64 + 4 * d4);
            }
            smu[SWH + (4 * d4 + 0) * 68 + s2] = hv.x;
            smu[SWH + (4 * d4 + 1) * 68 + s2] = hv.y;
            smu[SWH + (4 * d4 + 2) * 68 + s2] = hv.z;
            smu[SWH + (4 * d4 + 3) * 68 + s2] = hv.w;
            smu[SWL + (4 * d4 + 0) * 68 + s2] = lv.x;
            smu[SWL + (4 * d4 + 1) * 68 + s2] = lv.y;
            smu[SWL + (4 * d4 + 2) * 68 + s2] = lv.z;
            smu[SWL + (4 * d4 + 3) * 68 + s2] = lv.w;
        }
        __syncthreads();   // gathers done before P overwrites RS

        // P = exp(S1 + R - SHIFT) with causal mask; store to RS cols 0..63
#pragma unroll
        for (int m = 0; m < 4; m++) {
            int c = 32 * h + 8 * m + 2 * lt;
            int jg = j0 + c;
            float p0 = (jg     <= i0 + r1) ? __expf(s1[m][0] + rg[m][0] - SHIFT) : 0.f;
            float p1 = (jg + 1 <= i0 + r1) ? __expf(s1[m][1] + rg[m][1] - SHIFT) : 0.f;
            float p2 = (jg     <= i0 + r2) ? __expf(s1[m][2] + rg[m][2] - SHIFT) : 0.f;
            float p3 = (jg + 1 <= i0 + r2) ? __expf(s1[m][3] + rg[m][3] - SHIFT) : 0.f;
            rs0 += p0 + p1; rs1 += p2 + p3;
            smf[SRS + r1 * 132 + c]     = p0;
            smf[SRS + r1 * 132 + c + 1] = p1;
            smf[SRS + r2 * 132 + c]     = p2;
            smf[SRS + r2 * 132 + c + 1] = p3;
        }
        __syncthreads();

        // coalesced aw write from smem
        if (write_aw) {
#pragma unroll
            for (int k = 0; k < 4; k++) {
                int idx = tid + k * 256;
                int r = idx >> 4, c4 = idx & 15;
                const float* p = smf + SRS + r * 132 + 4 * c4;
                *(float4*)(aw + ((size_t)bh * LSEQ + i0 + r) * LSEQ + j0 + 4 * c4) =
                    make_float4(p[0], p[1], p[2], p[3]);
            }
        }

        // O1 = P V  (A = P split on the fly from fp32 smem)
#pragma unroll
        for (int ks = 0; ks < 4; ks++) {
            u32 ah[4], al[4];
            int b1i = SRS + r1 * 132 + 16 * ks + 2 * lt;
            int b2i = SRS + r2 * 132 + 16 * ks + 2 * lt;
            split2(smf[b1i],     smf[b1i + 1], ah[0], al[0]);
            split2(smf[b2i],     smf[b2i + 1], ah[1], al[1]);
            split2(smf[b1i + 8], smf[b1i + 9], ah[2], al[2]);
            split2(smf[b2i + 8], smf[b2i + 9], ah[3], al[3]);
#pragma unroll
            for (int m = 0; m < 4; m++) {
                int vb = SKH + (32 * h + 8 * m + lr) * 36 + 8 * ks + lt;
                mma3(oacc[m], ah, al, smu[vb], smu[vb + 4], smu[vb + 2304], smu[vb + 2308]);
            }
        }
        // O2 = Pd WVwin, ks restricted to band [g, g+4]; Pd[r][k] = P[r][r-k+63]
#pragma unroll
        for (int q = 0; q < 5; q++) {
            int ks = g + q;
            int k0 = 16 * ks + 2 * lt;
            u32 ah[4], al[4];
            int c1a = r1 - k0 + 63, c2a = r2 - k0 + 63;
#pragma unroll
            for (int half = 0; half < 2; half++) {
                int c1 = c1a - 8 * half, c2 = c2a - 8 * half;
                float x0 = (c1 >= 0 && c1 <= 63) ? smf[SRS + r1 * 132 + c1] : 0.f;
                float x1 = (c1 >= 1 && c1 <= 64) ? smf[SRS + r1 * 132 + c1 - 1] : 0.f;
                split2(x0, x1, ah[2 * half], al[2 * half]);
                float y0 = (c2 >= 0 && c2 <= 63) ? smf[SRS + r2 * 132 + c2] : 0.f;
                float y1 = (c2 >= 1 && c2 <= 64) ? smf[SRS + r2 * 132 + c2 - 1] : 0.f;
                split2(y0, y1, ah[2 * half + 1], al[2 * half + 1]);
            }
#pragma unroll
            for (int m = 0; m < 4; m++) {
                int wb = SWH + (32 * h + 8 * m + lr) * 68 + 8 * ks + lt;
                mma3(oacc[m], ah, al, smu[wb], smu[wb + 4], smu[wb + 4608], smu[wb + 4612]);
            }
        }
    }

    // finalize: reduce rowsums over lt group; both column-half warps contribute
    rs0 += __shfl_xor_sync(0xffffffffu, rs0, 1);
    rs0 += __shfl_xor_sync(0xffffffffu, rs0, 2);
    rs1 += __shfl_xor_sync(0xffffffffu, rs1, 1);
    rs1 += __shfl_xor_sync(0xffffffffu, rs1, 2);
    if (lt == 0) {
        atomicAdd(&rowsum[bh * LSEQ + i0 + r1], rs0);
        atomicAdd(&rowsum[bh * LSEQ + i0 + r2], rs1);
    }

    const int b = bh >> 3, head = bh & 7;
#pragma unroll
    for (int m = 0; m < 4; m++) {
        int d = head * DH + 32 * h + 8 * m + 2 * lt;
        float* d1 = att + ((size_t)(b * LSEQ + i0 + r1)) * DMODEL + d;
        float* d2 = att + ((size_t)(b * LSEQ + i0 + r2)) * DMODEL + d;
        atomicAdd(d1,     oacc[m][0]);
        atomicAdd(d1 + 1, oacc[m][1]);
        atomicAdd(d2,     oacc[m][2]);
        atomicAdd(d2 + 1, oacc[m][3]);
    }
}

// ---------------------------------------------------------------------------
__global__ __launch_bounds__(256) void scale_att(float* __restrict__ att,
                                                 const float* __restrict__ rowsum)
{
    int idx = blockIdx.x * 256 + threadIdx.x;
    int m = idx >> 7, c4 = idx & 127;
    int h = c4 >> 4;
    int b = m >> 11, l = m & (LSEQ - 1);
    float inv = 1.0f / rowsum[(b * NHEAD + h) * LSEQ + l];
    float4* p = (float4*)(att + (size_t)m * DMODEL) + c4;
    float4 v = *p;
    v.x *= inv; v.y *= inv; v.z *= inv; v.w *= inv;
    *p = v;
}

__global__ __launch_bounds__(256) void norm_aw(float* __restrict__ aw,
                                               const float* __restrict__ rowsum)
{
    const int row = blockIdx.x;
    const int i = row & (LSEQ - 1);
    const float inv = 1.0f / rowsum[row];
    float4* p = (float4*)(aw + (size_t)row * LSEQ);
#pragma unroll
    for (int k = 0; k < 2; k++) {
        int c4 = threadIdx.x + k * 256;
        int j = c4 * 4;
        float4 v;
        if (j + 3 <= i) {
            v = p[c4];
            v.x *= inv; v.y *= inv; v.z *= inv; v.w *= inv;
        } else if (j > i) {
            v = make_float4(0.f, 0.f, 0.f, 0.f);
        } else {
            v = p[c4];
            v.x = (j     <= i) ? v.x * inv : 0.f;
            v.y = (j + 1 <= i) ? v.y * inv : 0.f;
            v.z = (j + 2 <= i) ? v.z * inv : 0.f;
            v.w = (j + 3 <= i) ? v.w * inv : 0.f;
        }
        p[c4] = v;
    }
}

// ---------------------------------------------------------------------------
extern "C" void kernel_launch(void* const* d_in, const int* in_sizes, int n_in,
                              void* d_out, int out_size)
{
    const float* q       = (const float*)d_in[0];
    const float* k       = (const float*)d_in[1];
    const float* v       = (const float*)d_in[2];
    const float* wq      = (const float*)d_in[4];
    const float* bq      = (const float*)d_in[5];
    const float* wk      = (const float*)d_in[6];
    const float* bk      = (const float*)d_in[7];
    const float* wv      = (const float*)d_in[8];
    const float* bv      = (const float*)d_in[9];
    const float* wo      = (const float*)d_in[10];
    const float* bo      = (const float*)d_in[11];
    const float* key_rel = (const float*)d_in[12];
    const float* val_rel = (const float*)d_in[13];

    float* out = (float*)d_out;
    const long long OUT_ELEMS = (long long)BATCH * LSEQ * DMODEL;
    const long long AW_ELEMS  = (long long)BH * LSEQ * LSEQ;
    const int write_aw = ((long long)out_size >= OUT_ELEMS + AW_ELEMS) ? 1 : 0;
    float* aw = out + OUT_ELEMS;

    float *vh, *att, *rsum;
    cudaGetSymbolAddress((void**)&vh,   g_vh);
    cudaGetSymbolAddress((void**)&att,  g_att);
    cudaGetSymbolAddress((void**)&rsum, g_rowsum);

    cudaFuncSetAttribute(attn_mma, cudaFuncAttributeMaxDynamicSharedMemorySize, SMEM_BYTES);

    cudaMemsetAsync(att,  0, (size_t)MROWS * DMODEL * sizeof(float));
    cudaMemsetAsync(rsum, 0, (size_t)BH * LSEQ * sizeof(float));

    prep_rel<<<128, 256>>>(key_rel, val_rel);

    dim3 gGrid3(MROWS / 64, DMODEL / 64, 3);
    gemm512<<<gGrid3, 256>>>(q, wq, bq, nullptr,
                             k, wk, bk,
                             v, wv, bv, vh, 1);

    attn_mma<<<dim3(32, 2, BH), 256, SMEM_BYTES>>>(vh, aw, att, rsum, write_aw);

    scale_att<<<2048, 256>>>(att, rsum);
    if (write_aw)
        norm_aw<<<BH * LSEQ, 256>>>(aw, rsum);

    dim3 gGrid(MROWS / 64, DMODEL / 64, 1);
    gemm512<<<gGrid, 256>>>(att, wo, bo, out,
                            att, wo, bo,
                            att, wo, bo, out, 0);
}

// round 17
// speedup vs baseline: 1.5331x; 1.0144x over previous
#include <cuda_runtime.h>

#define LSEQ   2048
#define DMODEL 512
#define NHEAD  8
#define DH     64
#define BATCH  2
#define BH     16
#define MROWS  4096
#define SHIFT  48.0f

typedef unsigned int u32;
typedef unsigned long long ull;

// ---------------- f32x2 helpers (projection GEMMs) ----------------
__device__ __forceinline__ ull dup2(float x) {
    ull r; asm("mov.b64 %0, {%1, %1};" : "=l"(r) : "f"(x)); return r;
}
__device__ __forceinline__ void unpack2(ull v, float& lo, float& hi) {
    asm("mov.b64 {%0, %1}, %2;" : "=f"(lo), "=f"(hi) : "l"(v));
}
__device__ __forceinline__ ull fma2(ull a, ull b, ull c) {
    ull d; asm("fma.rn.f32x2 %0, %1, %2, %3;" : "=l"(d) : "l"(a), "l"(b), "l"(c)); return d;
}

// ---------------- bf16 split + mma helpers ----------------
__device__ __forceinline__ void split2(float f0, float f1, u32& h, u32& l) {
    asm("cvt.rn.bf16x2.f32 %0, %1, %2;" : "=r"(h) : "f"(f1), "f"(f0));
    float h0 = __uint_as_float(h << 16);
    float h1 = __uint_as_float(h & 0xffff0000u);
    asm("cvt.rn.bf16x2.f32 %0, %1, %2;" : "=r"(l) : "f"(f1 - h1), "f"(f0 - h0));
}
__device__ __forceinline__ void mma_bf(float* c, const u32* a, u32 b0, u32 b1) {
    asm volatile(
        "mma.sync.aligned.m16n8k16.row.col.f32.bf16.bf16.f32 "
        "{%0,%1,%2,%3},{%4,%5,%6,%7},{%8,%9},{%0,%1,%2,%3};"
        : "+f"(c[0]), "+f"(c[1]), "+f"(c[2]), "+f"(c[3])
        : "r"(a[0]), "r"(a[1]), "r"(a[2]), "r"(a[3]), "r"(b0), "r"(b1));
}
__device__ __forceinline__ void mma3(float* c, const u32* ah, const u32* al,
                                     u32 bh0, u32 bh1, u32 bl0, u32 bl1) {
    mma_bf(c, ah, bh0, bh1);
    mma_bf(c, ah, bl0, bl1);
    mma_bf(c, al, bh0, bh1);
}

// ---------------- scratch ----------------
__device__ float g_vh[BH * LSEQ * DH];
__device__ float g_att[MROWS * DMODEL];
__device__ float g_rowsum[BH * LSEQ];
__device__ u32 g_qkp_h[2 * BH * LSEQ * 32];
__device__ u32 g_qkp_l[2 * BH * LSEQ * 32];
__device__ u32 g_kr_h[LSEQ * 32];
__device__ u32 g_kr_l[LSEQ * 32];
__device__ u32 g_vp_h[1025 * 64];
__device__ u32 g_vp_l[1025 * 64];

// ---------------------------------------------------------------------------
// prep: pre-split key_rel / val_rel into packed bf16 hi/lo
// ---------------------------------------------------------------------------
__global__ __launch_bounds__(256) void prep_rel(const float* __restrict__ key_rel,
                                                const float* __restrict__ val_rel)
{
    int tid = blockIdx.x * 256 + threadIdx.x;
    {
        int delta = tid >> 4, d4 = tid & 15;
        float4 f = *(const float4*)(key_rel + (size_t)(2047 - delta) * DH + 4 * d4);
        u32 h0, l0, h1, l1;
        split2(f.x, f.y, h0, l0);
        split2(f.z, f.w, h1, l1);
        g_kr_h[delta * 32 + 2 * d4] = h0; g_kr_h[delta * 32 + 2 * d4 + 1] = h1;
        g_kr_l[delta * 32 + 2 * d4] = l0; g_kr_l[delta * 32 + 2 * d4 + 1] = l1;
    }
    if (tid < 1025 * 16) {
        int idx = tid >> 4, d4 = tid & 15;
        int m = idx - 1;
        int da = 2 * m + 1, db = 2 * m + 2;
        float4 fa = make_float4(0.f, 0.f, 0.f, 0.f), fb = fa;
        if (da >= 0 && da < LSEQ)
            fa = *(const float4*)(val_rel + (size_t)(2047 - da) * DH + 4 * d4);
        if (db >= 0 && db < LSEQ)
            fb = *(const float4*)(val_rel + (size_t)(2047 - db) * DH + 4 * d4);
        const float* pa = (const float*)&fa;
        const float* pb = (const float*)&fb;
#pragma unroll
        for (int e = 0; e < 4; e++) {
            u32 hp, lp;
            split2(pa[e], pb[e], hp, lp);
            g_vp_h[idx * 64 + 4 * d4 + e] = hp;
            g_vp_l[idx * 64 + 4 * d4 + e] = lp;
        }
    }
}

// ---------------------------------------------------------------------------
// 64x64-tiled GEMM (f32x2). head_layout=1: z=0/1 write packed bf16 Q/K,
// z=2 writes fp32 V in head layout. head_layout=0: plain fp32 GEMM.
// ---------------------------------------------------------------------------
__global__ __launch_bounds__(256) void gemm512(const float* __restrict__ A0,
                                               const float* __restrict__ W0,
                                               const float* __restrict__ b0,
                                               float* __restrict__ o0,
                                               const float* __restrict__ A1,
                                               const float* __restrict__ W1,
                                               const float* __restrict__ b1,
                                               const float* __restrict__ A2,
                                               const float* __restrict__ W2,
                                               const float* __restrict__ b2,
                                               float* __restrict__ o2,
                                               int head_layout)
{
    const float* A = A0; const float* W = W0; const float* bias = b0;
    if (blockIdx.z == 1) { A = A1; W = W1; bias = b1; }
    if (blockIdx.z == 2) { A = A2; W = W2; bias = b2; }

    __shared__ float As[64 * 16];
    __shared__ float Ws[16 * 64];
    const int tid = threadIdx.x;
    const int tx = tid & 15, ty = tid >> 4;
    const int m0 = blockIdx.x * 64;
    const int n0 = blockIdx.y * 64;

    ull acc2[4][2] = {};

    for (int k0 = 0; k0 < DMODEL; k0 += 16) {
        {
            int idx = tid * 4;
            int r = idx >> 4, c = idx & 15;
            *(float4*)(As + idx) = *(const float4*)(A + (size_t)(m0 + r) * DMODEL + k0 + c);
            int kk = idx >> 6, cc = idx & 63;
            *(float4*)(Ws + idx) = *(const float4*)(W + (size_t)(k0 + kk) * DMODEL + n0 + cc);
        }
        __syncthreads();
#pragma unroll
        for (int kk = 0; kk < 16; kk++) {
            ulonglong2 bp = *(const ulonglong2*)(Ws + kk * 64 + tx * 4);
#pragma unroll
            for (int u = 0; u < 4; u++) {
                ull ad = dup2(As[(ty * 4 + u) * 16 + kk]);
                acc2[u][0] = fma2(ad, bp.x, acc2[u][0]);
                acc2[u][1] = fma2(ad, bp.y, acc2[u][1]);
            }
        }
        __syncthreads();
    }

    float4 bb = *(const float4*)(bias + n0 + tx * 4);
#pragma unroll
    for (int u = 0; u < 4; u++) {
        int m = m0 + ty * 4 + u;
        float4 o;
        unpack2(acc2[u][0], o.x, o.y);
        unpack2(acc2[u][1], o.z, o.w);
        o.x += bb.x; o.y += bb.y; o.z += bb.z; o.w += bb.w;
        if (head_layout) {
            int b = m >> 11, l = m & (LSEQ - 1), h = n0 >> 6;
            if (blockIdx.z == 2) {
                *(float4*)(o2 + (((size_t)(b * NHEAD + h) * LSEQ + l) * DH + tx * 4)) = o;
            } else {
                u32 h0, l0, h1, l1;
                split2(o.x, o.y, h0, l0);
                split2(o.z, o.w, h1, l1);
                size_t base = (size_t)blockIdx.z * (BH * LSEQ * 32)
                            + ((size_t)(b * NHEAD + h) * LSEQ + l) * 32 + 2 * tx;
                g_qkp_h[base] = h0; g_qkp_h[base + 1] = h1;
                g_qkp_l[base] = l0; g_qkp_l[base + 1] = l1;
            }
        } else {
            *(float4*)(o0 + (size_t)m * DMODEL + n0 + tx * 4) = o;
        }
    }
}

// ---------------------------------------------------------------------------
// Tensor-core attention. 64x64 tiles, 8 warps, j-split (2 CTAs/i-tile), 2/SM.
// Adds: zero-fill of fully-masked aw tiles (t > ib), split across the 2 CTAs.
// ---------------------------------------------------------------------------
#define SQH 0
#define SQL 2304
#define SKH 4608
#define SKL 6912
#define SWH 9216
#define SWL 13824
#define SRS 18432
#define SMEM_BYTES (26880 * 4)

__global__ __launch_bounds__(256, 2) void attn_mma(const float* __restrict__ vh,
                                                   float* __restrict__ aw,
                                                   float* __restrict__ att,
                                                   float* __restrict__ rowsum,
                                                   int write_aw)
{
    extern __shared__ u32 smu[];
    float* smf = (float*)smu;

    const int tid = threadIdx.x;
    const int w = tid >> 5, g = w & 3, h = w >> 2;
    const int lane = tid & 31, lr = lane >> 2, lt = lane & 3;
    const int r1 = 16 * g + lr, r2 = r1 + 8;

    const int ib = 31 - blockIdx.x;
    const int hh = blockIdx.y;
    const int i0 = ib * 64;
    const int bh = blockIdx.z;
    const int nt = ib + 1, n0h = (nt + 1) >> 1;
    const int t0 = hh ? n0h : 0;
    const int t1 = hh ? nt : n0h;

    // ---- zero-fill fully-masked aw tiles of this i-row (before any early exit)
    if (write_aw) {
        const float4 z = make_float4(0.f, 0.f, 0.f, 0.f);
        for (int t = ib + 1 + hh; t < 32; t += 2) {
            const int j0 = t * 64;
#pragma unroll
            for (int k = 0; k < 4; k++) {
                int idx = tid + k * 256;
                int r = idx >> 4, c4 = idx & 15;
                *(float4*)(aw + ((size_t)bh * LSEQ + i0 + r) * LSEQ + j0 + 4 * c4) = z;
            }
        }
    }
    if (t0 >= t1) return;

    // Q fill: plain ull copies of pre-packed pairs
    const u32* qph = g_qkp_h + ((size_t)bh * LSEQ + i0) * 32;
    const u32* qpl = g_qkp_l + ((size_t)bh * LSEQ + i0) * 32;
#pragma unroll
    for (int k = 0; k < 4; k++) {
        int idx = tid + k * 256;
        int r = idx >> 4, d4 = idx & 15;
        ull hv = *(const ull*)(qph + r * 32 + 2 * d4);
        ull lv = *(const ull*)(qpl + r * 32 + 2 * d4);
        smu[SQH + r * 36 + 2 * d4]     = (u32)hv;
        smu[SQH + r * 36 + 2 * d4 + 1] = (u32)(hv >> 32);
        smu[SQL + r * 36 + 2 * d4]     = (u32)lv;
        smu[SQL + r * 36 + 2 * d4 + 1] = (u32)(lv >> 32);
    }

    float rs0 = 0.f, rs1 = 0.f;
    float oacc[4][4] = {};

    for (int t = t0; t < t1; t++) {
        const int j0 = t * 64;
        const int base = i0 - j0;

        __syncthreads();
        // K fill: pre-packed copies
        const u32* kph = g_qkp_h + (size_t)(BH * LSEQ * 32) + ((size_t)bh * LSEQ + j0) * 32;
        const u32* kpl = g_qkp_l + (size_t)(BH * LSEQ * 32) + ((size_t)bh * LSEQ + j0) * 32;
#pragma unroll
        for (int k = 0; k < 4; k++) {
            int idx = tid + k * 256;
            int r = idx >> 4, d4 = idx & 15;
            ull hv = *(const ull*)(kph + r * 32 + 2 * d4);
            ull lv = *(const ull*)(kpl + r * 32 + 2 * d4);
            smu[SKH + r * 36 + 2 * d4]     = (u32)hv;
            smu[SKH + r * 36 + 2 * d4 + 1] = (u32)(hv >> 32);
            smu[SKL + r * 36 + 2 * d4]     = (u32)lv;
            smu[SKL + r * 36 + 2 * d4 + 1] = (u32)(lv >> 32);
        }
        // W window fill from g_kr (delta = base-63+s)
#pragma unroll
        for (int k = 0; k < 8; k++) {
            int idx = tid + k * 256;
            int s = idx >> 4, d4 = idx & 15;
            int delta = base - 63 + s;
            u32 a = 0, b = 0, c = 0, d = 0;
            if (delta >= 0 && delta < LSEQ) {
                ull hv = *(const ull*)(g_kr_h + delta * 32 + 2 * d4);
                ull lv = *(const ull*)(g_kr_l + delta * 32 + 2 * d4);
                a = (u32)hv; b = (u32)(hv >> 32);
                c = (u32)lv; d = (u32)(lv >> 32);
            }
            smu[SWH + s * 36 + 2 * d4]     = a;
            smu[SWH + s * 36 + 2 * d4 + 1] = b;
            smu[SWL + s * 36 + 2 * d4]     = c;
            smu[SWL + s * 36 + 2 * d4 + 1] = d;
        }
        __syncthreads();

        // S1 = Q K^T (4 n-tiles) and R = Q Wwin^T (5 band tiles)
        float s1[4][4] = {};
        float ra[5][4] = {};
#pragma unroll
        for (int ks = 0; ks < 4; ks++) {
            u32 ah[4], al[4];
            int qa = r1 * 36 + 8 * ks + lt;
            ah[0] = smu[SQH + qa];     ah[1] = smu[SQH + qa + 288];
            ah[2] = smu[SQH + qa + 4]; ah[3] = smu[SQH + qa + 292];
            al[0] = smu[SQL + qa];     al[1] = smu[SQL + qa + 288];
            al[2] = smu[SQL + qa + 4]; al[3] = smu[SQL + qa + 292];
#pragma unroll
            for (int m = 0; m < 4; m++) {
                int kb = SKH + (32 * h + 8 * m + lr) * 36 + 8 * ks + lt;
                mma3(s1[m], ah, al, smu[kb], smu[kb + 4], smu[kb + 2304], smu[kb + 2308]);
            }
#pragma unroll
            for (int q = 0; q < 5; q++) {
                int wb = SWH + (8 * (2 * g + 5 * h + q) + lr) * 36 + 8 * ks + lt;
                mma3(ra[q], ah, al, smu[wb], smu[wb + 4], smu[wb + 4608], smu[wb + 4612]);
            }
        }
        // stage R band into RS fp32 [64][132]
#pragma unroll
        for (int q = 0; q < 5; q++) {
            int c0 = 8 * (2 * g + 5 * h + q) + 2 * lt;
            smf[SRS + r1 * 132 + c0]     = ra[q][0];
            smf[SRS + r1 * 132 + c0 + 1] = ra[q][1];
            smf[SRS + r2 * 132 + c0]     = ra[q][2];
            smf[SRS + r2 * 132 + c0 + 1] = ra[q][3];
        }
        __syncthreads();

        // gather rel logits: s = r - c + 63
        float rg[4][4];
#pragma unroll
        for (int m = 0; m < 4; m++) {
            int c = 32 * h + 8 * m + 2 * lt;
            rg[m][0] = smf[SRS + r1 * 132 + (r1 - c + 63)];
            rg[m][1] = smf[SRS + r1 * 132 + (r1 - c + 62)];
            rg[m][2] = smf[SRS + r2 * 132 + (r2 - c + 63)];
            rg[m][3] = smf[SRS + r2 * 132 + (r2 - c + 62)];
        }
        // Vt fill [d][j2] stride 36 (overwrites K region)
        const float* vbase = vh + ((size_t)bh * LSEQ + j0) * DH;
#pragma unroll
        for (int k = 0; k < 2; k++) {
            int idx = tid + k * 256;
            int j2 = idx >> 4, d4 = idx & 15;
            float4 fa = *(const float4*)(vbase + (2 * j2) * 64 + 4 * d4);
            float4 fb = *(const float4*)(vbase + (2 * j2 + 1) * 64 + 4 * d4);
            const float* pa = (const float*)&fa;
            const float* pb = (const float*)&fb;
#pragma unroll
            for (int e = 0; e < 4; e++) {
                u32 hp, lp;
                split2(pa[e], pb[e], hp, lp);
                smu[SKH + (4 * d4 + e) * 36 + j2] = hp;
                smu[SKL + (4 * d4 + e) * 36 + j2] = lp;
            }
        }
        // WVt fill [d][s2] stride 68 from g_vp (overwrites W region)
#pragma unroll
        for (int k = 0; k < 4; k++) {
            int idx = tid + k * 256;
            int s2 = idx >> 4, d4 = idx & 15;
            int vidx = (base >> 1) + s2 - 31;
            uint4 hv = make_uint4(0u, 0u, 0u, 0u), lv = hv;
            if (vidx >= 0 && vidx <= 1024) {
                hv = *(const uint4*)(g_vp_h + vidx * 64 + 4 * d4);
                lv = *(const uint4*)(g_vp_l + vidx * 64 + 4 * d4);
            }
            smu[SWH + (4 * d4 + 0) * 68 + s2] = hv.x;
            smu[SWH + (4 * d4 + 1) * 68 + s2] = hv.y;
            smu[SWH + (4 * d4 + 2) * 68 + s2] = hv.z;
            smu[SWH + (4 * d4 + 3) * 68 + s2] = hv.w;
            smu[SWL + (4 * d4 + 0) * 68 + s2] = lv.x;
            smu[SWL + (4 * d4 + 1) * 68 + s2] = lv.y;
            smu[SWL + (4 * d4 + 2) * 68 + s2] = lv.z;
            smu[SWL + (4 * d4 + 3) * 68 + s2] = lv.w;
        }
        __syncthreads();   // gathers done before P overwrites RS

        // P = exp(S1 + R - SHIFT) with causal mask; store to RS cols 0..63
#pragma unroll
        for (int m = 0; m < 4; m++) {
            int c = 32 * h + 8 * m + 2 * lt;
            int jg = j0 + c;
            float p0 = (jg     <= i0 + r1) ? __expf(s1[m][0] + rg[m][0] - SHIFT) : 0.f;
            float p1 = (jg + 1 <= i0 + r1) ? __expf(s1[m][1] + rg[m][1] - SHIFT) : 0.f;
            float p2 = (jg     <= i0 + r2) ? __expf(s1[m][2] + rg[m][2] - SHIFT) : 0.f;
            float p3 = (jg + 1 <= i0 + r2) ? __expf(s1[m][3] + rg[m][3] - SHIFT) : 0.f;
            rs0 += p0 + p1; rs1 += p2 + p3;
            smf[SRS + r1 * 132 + c]     = p0;
            smf[SRS + r1 * 132 + c + 1] = p1;
            smf[SRS + r2 * 132 + c]     = p2;
            smf[SRS + r2 * 132 + c + 1] = p3;
        }
        __syncthreads();

        // coalesced aw write from smem
        if (write_aw) {
#pragma unroll
            for (int k = 0; k < 4; k++) {
                int idx = tid + k * 256;
                int r = idx >> 4, c4 = idx & 15;
                const float* p = smf + SRS + r * 132 + 4 * c4;
                *(float4*)(aw + ((size_t)bh * LSEQ + i0 + r) * LSEQ + j0 + 4 * c4) =
                    make_float4(p[0], p[1], p[2], p[3]);
            }
        }

        // O1 = P V  (A = P split on the fly from fp32 smem)
#pragma unroll
        for (int ks = 0; ks < 4; ks++) {
            u32 ah[4], al[4];
            int b1i = SRS + r1 * 132 + 16 * ks + 2 * lt;
            int b2i = SRS + r2 * 132 + 16 * ks + 2 * lt;
            split2(smf[b1i],     smf[b1i + 1], ah[0], al[0]);
            split2(smf[b2i],     smf[b2i + 1], ah[1], al[1]);
            split2(smf[b1i + 8], smf[b1i + 9], ah[2], al[2]);
            split2(smf[b2i + 8], smf[b2i + 9], ah[3], al[3]);
#pragma unroll
            for (int m = 0; m < 4; m++) {
                int vb = SKH + (32 * h + 8 * m + lr) * 36 + 8 * ks + lt;
                mma3(oacc[m], ah, al, smu[vb], smu[vb + 4], smu[vb + 2304], smu[vb + 2308]);
            }
        }
        // O2 = Pd WVwin, ks restricted to band [g, g+4]; Pd[r][k] = P[r][r-k+63]
#pragma unroll
        for (int q = 0; q < 5; q++) {
            int ks = g + q;
            int k0 = 16 * ks + 2 * lt;
            u32 ah[4], al[4];
            int c1a = r1 - k0 + 63, c2a = r2 - k0 + 63;
#pragma unroll
            for (int half = 0; half < 2; half++) {
                int c1 = c1a - 8 * half, c2 = c2a - 8 * half;
                float x0 = (c1 >= 0 && c1 <= 63) ? smf[SRS + r1 * 132 + c1] : 0.f;
                float x1 = (c1 >= 1 && c1 <= 64) ? smf[SRS + r1 * 132 + c1 - 1] : 0.f;
                split2(x0, x1, ah[2 * half], al[2 * half]);
                float y0 = (c2 >= 0 && c2 <= 63) ? smf[SRS + r2 * 132 + c2] : 0.f;
                float y1 = (c2 >= 1 && c2 <= 64) ? smf[SRS + r2 * 132 + c2 - 1] : 0.f;
                split2(y0, y1, ah[2 * half + 1], al[2 * half + 1]);
            }
#pragma unroll
            for (int m = 0; m < 4; m++) {
                int wb = SWH + (32 * h + 8 * m + lr) * 68 + 8 * ks + lt;
                mma3(oacc[m], ah, al, smu[wb], smu[wb + 4], smu[wb + 4608], smu[wb + 4612]);
            }
        }
    }

    // finalize: reduce rowsums over lt group; both column-half warps contribute
    rs0 += __shfl_xor_sync(0xffffffffu, rs0, 1);
    rs0 += __shfl_xor_sync(0xffffffffu, rs0, 2);
    rs1 += __shfl_xor_sync(0xffffffffu, rs1, 1);
    rs1 += __shfl_xor_sync(0xffffffffu, rs1, 2);
    if (lt == 0) {
        atomicAdd(&rowsum[bh * LSEQ + i0 + r1], rs0);
        atomicAdd(&rowsum[bh * LSEQ + i0 + r2], rs1);
    }

    const int b = bh >> 3, head = bh & 7;
#pragma unroll
    for (int m = 0; m < 4; m++) {
        int d = head * DH + 32 * h + 8 * m + 2 * lt;
        float* d1 = att + ((size_t)(b * LSEQ + i0 + r1)) * DMODEL + d;
        float* d2 = att + ((size_t)(b * LSEQ + i0 + r2)) * DMODEL + d;
        atomicAdd(d1,     oacc[m][0]);
        atomicAdd(d1 + 1, oacc[m][1]);
        atomicAdd(d2,     oacc[m][2]);
        atomicAdd(d2 + 1, oacc[m][3]);
    }
}

// ---------------------------------------------------------------------------
__global__ __launch_bounds__(256) void scale_att(float* __restrict__ att,
                                                 const float* __restrict__ rowsum)
{
    int idx = blockIdx.x * 256 + threadIdx.x;
    int m = idx >> 7, c4 = idx & 127;
    int h = c4 >> 4;
    int b = m >> 11, l = m & (LSEQ - 1);
    float inv = 1.0f / rowsum[(b * NHEAD + h) * LSEQ + l];
    float4* p = (float4*)(att + (size_t)m * DMODEL) + c4;
    float4 v = *p;
    v.x *= inv; v.y *= inv; v.z *= inv; v.w *= inv;
    *p = v;
}

// ---------------------------------------------------------------------------
// norm_aw: lower-triangle only. Masked entries are exact 0 (written by
// attn_mma), and the upper tiles were zero-filled there too, so scaling the
// partial boundary group needs no masking (0 * inv == 0).
// ---------------------------------------------------------------------------
__global__ __launch_bounds__(256) void norm_aw(float* __restrict__ aw,
                                               const float* __restrict__ rowsum)
{
    const int row = blockIdx.x;
    const int i = row & (LSEQ - 1);
    const float inv = 1.0f / rowsum[row];
    float4* p = (float4*)(aw + (size_t)row * LSEQ);
    const int nfl = (i >> 2) + 1;          // float4 groups to scale
    for (int c4 = threadIdx.x; c4 < nfl; c4 += 256) {
        float4 v = p[c4];
        v.x *= inv; v.y *= inv; v.z *= inv; v.w *= inv;
        p[c4] = v;
    }
}

// ---------------------------------------------------------------------------
extern "C" void kernel_launch(void* const* d_in, const int* in_sizes, int n_in,
                              void* d_out, int out_size)
{
    const float* q       = (const float*)d_in[0];
    const float* k       = (const float*)d_in[1];
    const float* v       = (const float*)d_in[2];
    const float* wq      = (const float*)d_in[4];
    const float* bq      = (const float*)d_in[5];
    const float* wk      = (const float*)d_in[6];
    const float* bk      = (const float*)d_in[7];
    const float* wv      = (const float*)d_in[8];
    const float* bv      = (const float*)d_in[9];
    const float* wo      = (const float*)d_in[10];
    const float* bo      = (const float*)d_in[11];
    const float* key_rel = (const float*)d_in[12];
    const float* val_rel = (const float*)d_in[13];

    float* out = (float*)d_out;
    const long long OUT_ELEMS = (long long)BATCH * LSEQ * DMODEL;
    const long long AW_ELEMS  = (long long)BH * LSEQ * LSEQ;
    const int write_aw = ((long long)out_size >= OUT_ELEMS + AW_ELEMS) ? 1 : 0;
    float* aw = out + OUT_ELEMS;

    float *vh, *att, *rsum;
    cudaGetSymbolAddress((void**)&vh,   g_vh);
    cudaGetSymbolAddress((void**)&att,  g_att);
    cudaGetSymbolAddress((void**)&rsum, g_rowsum);

    cudaFuncSetAttribute(attn_mma, cudaFuncAttributeMaxDynamicSharedMemorySize, SMEM_BYTES);

    cudaMemsetAsync(att,  0, (size_t)MROWS * DMODEL * sizeof(float));
    cudaMemsetAsync(rsum, 0, (size_t)BH * LSEQ * sizeof(float));

    prep_rel<<<128, 256>>>(key_rel, val_rel);

    dim3 gGrid3(MROWS / 64, DMODEL / 64, 3);
    gemm512<<<gGrid3, 256>>>(q, wq, bq, nullptr,
                             k, wk, bk,
                             v, wv, bv, vh, 1);

    attn_mma<<<dim3(32, 2, BH), 256, SMEM_BYTES>>>(vh, aw, att, rsum, write_aw);

    scale_att<<<2048, 256>>>(att, rsum);
    if (write_aw)
        norm_aw<<<BH * LSEQ, 256>>>(aw, rsum);

    dim3 gGrid(MROWS / 64, DMODEL / 64, 1);
    gemm512<<<gGrid, 256>>>(att, wo, bo, out,
                            att, wo, bo,
                            att, wo, bo, out, 0);
}